// round 10
// baseline (speedup 1.0000x reference)
#include <cuda_runtime.h>
#include <cuda_fp16.h>
#include <cstdint>
#include <math_constants.h>

#define CDIM 256
#define KCODES 8192
#define NROWS 16384
#define NT 128              // codes per chunk
#define MT 128              // rows per CTA
#define NCHUNKS (KCODES / NT)
#define CAP 128             // candidate slots per row
#define MARGIN 4.0e-3f      // f16-accum screening margin (~10 sigma)
#define BSCALE 8192.0f      // emb pre-scale into f16 range
#define SINV   (2.0f / 8192.0f)
#define GTHREADS 512

// ---------------------------------------------------------------------------
// Device globals (allocation-free scratch)
// ---------------------------------------------------------------------------
__device__ __align__(16) __half g_Ah[(size_t)NROWS * CDIM];    // f16(z) [n][c]
__device__ __align__(16) __half g_Bh[(size_t)KCODES * CDIM];   // f16(8192*emb) [k][c]
__device__ float    g_A[NROWS];                          // exact ||x||^2 (strict seq)
__device__ float    g_C[KCODES];                         // exact ||e||^2 (strict seq)
__device__ unsigned g_candk[(size_t)NROWS * CAP];
__device__ float    g_cands[(size_t)NROWS * CAP];
__device__ int      g_cnt[NROWS];
__device__ float    g_thresh[NROWS];
__device__ int      g_idx[NROWS];
__device__ float    g_partial[NROWS / 64];

// ---------------------------------------------------------------------------
// Helpers
// ---------------------------------------------------------------------------
__device__ __forceinline__ uint32_t smem_to_u32(const void* p) {
    uint32_t a;
    asm("{ .reg .u64 t; cvta.to.shared.u64 t, %1; cvt.u32.u64 %0, t; }" : "=r"(a) : "l"(p));
    return a;
}
__device__ __forceinline__ unsigned f2ord(float f) {   // order-preserving float->uint
    unsigned u = __float_as_uint(f);
    return (u & 0x80000000u) ? ~u : (u | 0x80000000u);
}
__device__ __forceinline__ float ord2f(unsigned u) {
    return __uint_as_float((u & 0x80000000u) ? (u ^ 0x80000000u) : ~u);
}
__device__ __forceinline__ void ldsm4(uint32_t r[4], uint32_t addr) {
    asm volatile("ldmatrix.sync.aligned.m8n8.x4.shared.b16 {%0,%1,%2,%3}, [%4];"
                 : "=r"(r[0]), "=r"(r[1]), "=r"(r[2]), "=r"(r[3]) : "r"(addr));
}
// f16-accumulate HMMA: d,c are 2 regs (4 x f16)
__device__ __forceinline__ void mma_h16(uint32_t d[2], const uint32_t a[4],
                                        uint32_t b0, uint32_t b1) {
    asm("mma.sync.aligned.m16n8k16.row.col.f16.f16.f16.f16 "
        "{%0,%1}, {%2,%3,%4,%5}, {%6,%7}, {%0,%1};"
        : "+r"(d[0]), "+r"(d[1])
        : "r"(a[0]), "r"(a[1]), "r"(a[2]), "r"(a[3]), "r"(b0), "r"(b1));
}
__device__ __forceinline__ void cp16(uint32_t dst, const void* src) {
    asm volatile("cp.async.cg.shared.global [%0], [%1], 16;" :: "r"(dst), "l"(src) : "memory");
}
#define CP_COMMIT() asm volatile("cp.async.commit_group;" ::: "memory")
#define CP_WAIT0()  asm volatile("cp.async.wait_group 0;" ::: "memory")

// ---------------------------------------------------------------------------
// Prep kernels
// ---------------------------------------------------------------------------
__global__ void conv_a_kernel(const float* __restrict__ z) {   // z[b][c][hw] -> Ah[n][c]
    __shared__ float tile[32][33];
    int b = blockIdx.z, hw0 = blockIdx.x * 32, cb = blockIdx.y * 32;
    int tx = threadIdx.x & 31, ty = threadIdx.x >> 5;
    #pragma unroll
    for (int r = ty; r < 32; r += 8)
        tile[r][tx] = z[((size_t)b * CDIM + cb + r) * 1024 + hw0 + tx];
    __syncthreads();
    #pragma unroll
    for (int r = ty; r < 32; r += 8)
        g_Ah[((size_t)b * 1024 + hw0 + r) * CDIM + cb + tx] = __float2half_rn(tile[tx][r]);
}

__global__ void conv_b_kernel(const float* __restrict__ emb) {  // f16(8192*emb)
    int i = blockIdx.x * blockDim.x + threadIdx.x;   // over KCODES*CDIM/4
    float4 v = ((const float4*)emb)[i];
    __half2* dst = (__half2*)g_Bh;
    dst[i * 2]     = __floats2half2_rn(v.x * BSCALE, v.y * BSCALE);
    dst[i * 2 + 1] = __floats2half2_rn(v.z * BSCALE, v.w * BSCALE);
}

// C_k = strict-sequential sum of e^2 (bit-exact), smem-staged for coalescing.
__global__ __launch_bounds__(128)
void c_kernel(const float* __restrict__ emb) {
    __shared__ float tile[128][33];
    const int k0 = blockIdx.x * 128;
    const int tid = threadIdx.x;
    float s = 0.f;
    for (int cb = 0; cb < 8; cb++) {
        __syncthreads();
        for (int u = tid; u < 128 * 32; u += 128) {
            int r = u >> 5, cc = u & 31;   // warp = one 128B row: coalesced
            tile[r][cc] = emb[(size_t)(k0 + r) * CDIM + cb * 32 + cc];
        }
        __syncthreads();
        #pragma unroll
        for (int cc = 0; cc < 32; cc++) {
            float v = tile[tid][cc];
            s = __fadd_rn(s, __fmul_rn(v, v));
        }
    }
    g_C[k0 + tid] = s;
}

// A_n strict-sequential; loads batched 32-wide (MLP), accumulation order unchanged.
__global__ __launch_bounds__(256)
void a_kernel(const float* __restrict__ z) {
    int n = blockIdx.x * blockDim.x + threadIdx.x;
    int b = n >> 10, hw = n & 1023;
    const float* zp = z + (size_t)b * CDIM * 1024 + hw;
    float s = 0.f;
    for (int c0 = 0; c0 < CDIM; c0 += 32) {
        float v[32];
        #pragma unroll
        for (int u = 0; u < 32; u++) v[u] = __ldg(zp + (size_t)(c0 + u) * 1024);
        #pragma unroll
        for (int u = 0; u < 32; u++) s = __fadd_rn(s, __fmul_rn(v[u], v[u]));
    }
    g_A[n] = s;
}

// ---------------------------------------------------------------------------
// GEMM (HMMA mma.sync f16 inputs, f16 accumulate) + two-pass screening.
// 512 threads, 16 warps in 4(M) x 4(N) grid, warp tile 32x32.
// SMEM layout (bytes): As 0..64K, B0 64K..128K, B1 128K..192K,
//                      C_s 192K (+1KB), runmax (+512), cnt (+512)
// ---------------------------------------------------------------------------
#define SM_A 0
#define SM_B0 65536
#define SM_B1 131072
#define SM_C  196608
#define SM_RMAX (SM_C + 1024)
#define SM_CNT  (SM_RMAX + 512)
#define SM_TOTAL (SM_CNT + 512)

// async-copy 128 rows x 256 f16 (64KB) gmem->smem, per-row XOR swizzle
// (16B granule g of row r stored at granule g ^ (r&7): conflict-free LDSM)
__device__ __forceinline__ void cp_tile(uint32_t dst, const __half* gsrc, int tid) {
    const char* src = (const char*)gsrc;
    #pragma unroll
    for (int it = 0; it < 8; it++) {
        int u = it * GTHREADS + tid;       // 0..4095 granules of 16B
        int row = u >> 5, gr = u & 31;     // 32 granules (512B) per row
        cp16(dst + row * 512 + ((gr ^ (row & 7)) << 4), src + (size_t)u * 16);
    }
}

__global__ __launch_bounds__(GTHREADS, 1)
void gemm_screen_kernel() {
    extern __shared__ char smem[];
    const uint32_t smem_base = smem_to_u32(smem);
    const int tid = threadIdx.x;
    const int wid = tid >> 5, lane = tid & 31;
    const int wm = wid & 3, wn = wid >> 2;       // 4x4 warp grid
    const int g = lane >> 2, tg = lane & 3;
    const int n0 = blockIdx.x * MT;

    float*    C_s     = (float*)(smem + SM_C);
    unsigned* sh_rmax = (unsigned*)(smem + SM_RMAX);
    int*      sh_cnt  = (int*)(smem + SM_CNT);

    if (tid < 128) { sh_rmax[tid] = f2ord(-CUDART_INF_F); sh_cnt[tid] = 0; }

    // Prologue: async A tile + B chunk 0; C chunk 0 regular
    cp_tile(smem_base + SM_A, g_Ah + (size_t)n0 * CDIM, tid);
    cp_tile(smem_base + SM_B0, g_Bh, tid);
    CP_COMMIT();
    if (tid < 128) C_s[tid] = g_C[tid];
    CP_WAIT0();
    __syncthreads();

    const uint32_t As_base = smem_base + SM_A;

    for (int i = 0; i < NCHUNKS; i++) {
        const int cur = i & 1, nxt = cur ^ 1;

        // Async prefetch next B chunk (+C) — overlaps the whole MMA body
        if (i + 1 < NCHUNKS) {
            cp_tile(smem_base + (nxt ? SM_B1 : SM_B0),
                    g_Bh + (size_t)(i + 1) * NT * CDIM, tid);
            CP_COMMIT();
            if (tid < 128) C_s[nxt * 128 + tid] = g_C[(i + 1) * NT + tid];
        }

        // ---- compute chunk i: warp tile 32(M) x 32(N), f16 accumulators ----
        const uint32_t Bs_base = smem_base + (cur ? SM_B1 : SM_B0);
        uint32_t acc[2][4][2];   // [mt][nt][half-pair], each reg = 2 x f16
        #pragma unroll
        for (int mt = 0; mt < 2; mt++)
            #pragma unroll
            for (int nt = 0; nt < 4; nt++) { acc[mt][nt][0] = 0u; acc[mt][nt][1] = 0u; }

        #pragma unroll
        for (int ks = 0; ks < 16; ks++) {
            uint32_t a_frag[2][4];
            #pragma unroll
            for (int mt = 0; mt < 2; mt++) {
                int row = wm * 32 + mt * 16 + (lane & 15);
                int gr  = ks * 2 + (lane >> 4);
                ldsm4(a_frag[mt], As_base + row * 512 + ((gr ^ (row & 7)) << 4));
            }
            uint32_t b_frag[2][4];
            #pragma unroll
            for (int bp = 0; bp < 2; bp++) {
                int n  = wn * 32 + bp * 16 + ((lane >> 4) << 3) + (lane & 7);
                int gr = ks * 2 + ((lane >> 3) & 1);
                ldsm4(b_frag[bp], Bs_base + n * 512 + ((gr ^ (n & 7)) << 4));
            }
            #pragma unroll
            for (int mt = 0; mt < 2; mt++)
                #pragma unroll
                for (int bp = 0; bp < 2; bp++) {
                    mma_h16(acc[mt][bp * 2],     a_frag[mt], b_frag[bp][0], b_frag[bp][1]);
                    mma_h16(acc[mt][bp * 2 + 1], a_frag[mt], b_frag[bp][2], b_frag[bp][3]);
                }
        }

        // ---- PASS 1: scores (rescaled) + chunk row-max -> sh_rmax ----
        float sc[2][4][4];
        #pragma unroll
        for (int mt = 0; mt < 2; mt++) {
            float lmax[2] = {-CUDART_INF_F, -CUDART_INF_F};
            #pragma unroll
            for (int nt = 0; nt < 4; nt++)
                #pragma unroll
                for (int h = 0; h < 2; h++) {
                    __half2 hv = *reinterpret_cast<__half2*>(&acc[mt][nt][h]);
                    float p0 = __low2float(hv), p1 = __high2float(hv);
                    #pragma unroll
                    for (int q = 0; q < 2; q++) {
                        int col = wn * 32 + nt * 8 + tg * 2 + q;
                        float s = __fmaf_rn(SINV, q ? p1 : p0, -C_s[cur * 128 + col]);
                        sc[mt][nt][h * 2 + q] = s;
                        if (s > lmax[h]) lmax[h] = s;
                    }
                }
            #pragma unroll
            for (int h = 0; h < 2; h++) {
                lmax[h] = fmaxf(lmax[h], __shfl_xor_sync(0xffffffffu, lmax[h], 1));
                lmax[h] = fmaxf(lmax[h], __shfl_xor_sync(0xffffffffu, lmax[h], 2));
                if (tg == 0) {
                    int rl = wm * 32 + mt * 16 + h * 8 + g;
                    atomicMax(&sh_rmax[rl], f2ord(lmax[h]));
                }
            }
        }
        __syncthreads();   // runmax now includes this chunk (all wn quarters)

        // ---- PASS 2: insert candidates above updated threshold ----
        const int k0 = i * NT;
        #pragma unroll
        for (int mt = 0; mt < 2; mt++)
            #pragma unroll
            for (int h = 0; h < 2; h++) {
                int rl = wm * 32 + mt * 16 + h * 8 + g;
                float thr = ord2f(sh_rmax[rl]) - MARGIN;
                #pragma unroll
                for (int nt = 0; nt < 4; nt++)
                    #pragma unroll
                    for (int q = 0; q < 2; q++) {
                        float s = sc[mt][nt][h * 2 + q];
                        if (s > thr) {
                            int col = wn * 32 + nt * 8 + tg * 2 + q;
                            int slot = atomicAdd(&sh_cnt[rl], 1);
                            if (slot < CAP) {
                                g_candk[(size_t)(n0 + rl) * CAP + slot] = (unsigned)(k0 + col);
                                g_cands[(size_t)(n0 + rl) * CAP + slot] = s;
                            }
                        }
                    }
            }
        if (i + 1 < NCHUNKS) CP_WAIT0();   // B(i+1) landed during the MMA body
        __syncthreads();
    }

    if (tid < 128) {
        g_cnt[n0 + tid] = sh_cnt[tid];
        g_thresh[n0 + tid] = ord2f(sh_rmax[tid]) - MARGIN;
    }
}

// ---------------------------------------------------------------------------
// Exact reference-emulated distance (validated bit-exact in R2)
// ---------------------------------------------------------------------------
__device__ __forceinline__ float exact_d(const float* __restrict__ zp,
                                         const float* __restrict__ e,
                                         float A, float C) {
    float P = 0.f;
    #pragma unroll 16
    for (int c = 0; c < CDIM; c++)
        P = __fmaf_rn(__ldg(zp + (size_t)c * 1024), __ldg(e + c), P);
    float t = __fsub_rn(A, __fmul_rn(2.0f, P));
    return __fadd_rn(t, C);
}

// One warp per row: exact argmin (first-index tie-break) over candidate set.
__global__ __launch_bounds__(256)
void rescore_kernel(const float* __restrict__ z, const float* __restrict__ emb) {
    const int wid = threadIdx.x >> 5, lane = threadIdx.x & 31;
    const int n = blockIdx.x * 8 + wid;
    const int b = n >> 10, hw = n & 1023;
    const float* zp = z + (size_t)b * CDIM * 1024 + hw;
    const float A = g_A[n];
    const int cnt = g_cnt[n];
    const float thresh = g_thresh[n];

    float bd = CUDART_INF_F;
    int bi = 0x7fffffff;

    if (cnt <= CAP) {
        for (int base = 0; base < cnt; base += 32) {
            int l = base + lane;
            if (l < cnt) {
                float s = g_cands[(size_t)n * CAP + l];
                if (s >= thresh) {
                    int k = (int)g_candk[(size_t)n * CAP + l];
                    float d = exact_d(zp, emb + (size_t)k * CDIM, A, g_C[k]);
                    if (d < bd || (d == bd && k < bi)) { bd = d; bi = k; }
                }
            }
        }
    } else {  // overflow fallback: exact scan of all codes (safety net)
        for (int k = lane; k < KCODES; k += 32) {
            float d = exact_d(zp, emb + (size_t)k * CDIM, A, g_C[k]);
            if (d < bd || (d == bd && k < bi)) { bd = d; bi = k; }
        }
    }
    #pragma unroll
    for (int off = 16; off; off >>= 1) {
        float od = __shfl_down_sync(0xffffffffu, bd, off);
        int   oi = __shfl_down_sync(0xffffffffu, bi, off);
        if (od < bd || (od == bd && oi < bi)) { bd = od; bi = oi; }
    }
    if (lane == 0) g_idx[n] = bi;
}

// ---------------------------------------------------------------------------
// Quantize / losses / indices (validated in R2)
// ---------------------------------------------------------------------------
__global__ __launch_bounds__(256)
void quantize_kernel(const float* __restrict__ z, const float* __restrict__ emb,
                     float* __restrict__ out) {
    __shared__ int bidx_s[64];
    __shared__ float red[256];
    const int tid = threadIdx.x;
    const int n0 = blockIdx.x * 64;
    const int bimg = n0 >> 10, hw0 = n0 & 1023;
    const float* zb = z + (size_t)bimg * CDIM * 1024 + hw0;
    const size_t QELEMS = (size_t)NROWS * CDIM;

    if (tid < 64) {
        int k = g_idx[n0 + tid];
        bidx_s[tid] = k;
        out[QELEMS + 2 + n0 + tid] = (float)k;
    }
    __syncthreads();

    float lsum = 0.f;
    for (int e = tid; e < 64 * CDIM; e += 256) {
        int c = e >> 6, m = e & 63;
        float q  = emb[(size_t)bidx_s[m] * CDIM + c];
        float zv = zb[(size_t)c * 1024 + m];
        float d  = __fsub_rn(q, zv);
        out[(size_t)bimg * CDIM * 1024 + (size_t)c * 1024 + hw0 + m] = __fadd_rn(zv, d);
        lsum = __fmaf_rn(d, d, lsum);
    }
    red[tid] = lsum;
    __syncthreads();
    #pragma unroll
    for (int st = 128; st; st >>= 1) {
        if (tid < st) red[tid] += red[tid + st];
        __syncthreads();
    }
    if (tid == 0) g_partial[blockIdx.x] = red[0];
}

__global__ void finalize_kernel(float* __restrict__ out) {
    __shared__ float red[256];
    red[threadIdx.x] = g_partial[threadIdx.x];
    __syncthreads();
    #pragma unroll
    for (int st = 128; st; st >>= 1) {
        if (threadIdx.x < st) red[threadIdx.x] += red[threadIdx.x + st];
        __syncthreads();
    }
    if (threadIdx.x == 0) {
        const size_t QELEMS = (size_t)NROWS * CDIM;
        float loss = red[0] / (float)QELEMS;
        out[QELEMS]     = loss;
        out[QELEMS + 1] = 0.25f * loss;
    }
}

// ---------------------------------------------------------------------------
extern "C" void kernel_launch(void* const* d_in, const int* in_sizes, int n_in,
                              void* d_out, int out_size) {
    const float* z   = (const float*)d_in[0];
    const float* emb = (const float*)d_in[1];
    float* out = (float*)d_out;

    cudaFuncSetAttribute(gemm_screen_kernel,
                         cudaFuncAttributeMaxDynamicSharedMemorySize, SM_TOTAL);

    conv_a_kernel<<<dim3(32, 8, 16), 256>>>(z);
    conv_b_kernel<<<KCODES * CDIM / 4 / 256, 256>>>(emb);
    c_kernel<<<KCODES / 128, 128>>>(emb);
    a_kernel<<<NROWS / 256, 256>>>(z);
    gemm_screen_kernel<<<NROWS / MT, GTHREADS, SM_TOTAL>>>();
    rescore_kernel<<<NROWS / 8, 256>>>(z, emb);
    quantize_kernel<<<NROWS / 64, 256>>>(z, emb, out);
    finalize_kernel<<<1, 256>>>(out);
}

// round 11
// speedup vs baseline: 339.8027x; 339.8027x over previous
#include <cuda_runtime.h>
#include <cuda_bf16.h>
#include <cstdint>
#include <math_constants.h>

#define CDIM 256
#define KCODES 8192
#define NROWS 16384
#define NT 128              // codes per chunk
#define MT 128              // rows per CTA
#define NCHUNKS (KCODES / NT)
#define CAP 128             // candidate slots per row
#define MARGIN 1.0e-3f
#define GTHREADS 512

// ---------------------------------------------------------------------------
// Device globals (allocation-free scratch)
// ---------------------------------------------------------------------------
__device__ __align__(16) __nv_bfloat16 g_Abf[(size_t)NROWS * CDIM];   // [n][c]
__device__ __align__(16) __nv_bfloat16 g_Bbf[(size_t)KCODES * CDIM];  // [k][c]
__device__ float    g_A[NROWS];                          // exact ||x||^2 (strict seq)
__device__ float    g_C[KCODES];                         // exact ||e||^2 (strict seq)
__device__ unsigned g_candk[(size_t)NROWS * CAP];
__device__ float    g_cands[(size_t)NROWS * CAP];
__device__ int      g_cnt[NROWS];
__device__ float    g_thresh[NROWS];
__device__ int      g_idx[NROWS];
__device__ float    g_partial[NROWS / 64];

// ---------------------------------------------------------------------------
// Helpers
// ---------------------------------------------------------------------------
__device__ __forceinline__ uint32_t smem_to_u32(const void* p) {
    uint32_t a;
    asm("{ .reg .u64 t; cvta.to.shared.u64 t, %1; cvt.u32.u64 %0, t; }" : "=r"(a) : "l"(p));
    return a;
}
__device__ __forceinline__ unsigned f2ord(float f) {
    unsigned u = __float_as_uint(f);
    return (u & 0x80000000u) ? ~u : (u | 0x80000000u);
}
__device__ __forceinline__ float ord2f(unsigned u) {
    return __uint_as_float((u & 0x80000000u) ? (u ^ 0x80000000u) : ~u);
}
__device__ __forceinline__ void ldsm4(uint32_t r[4], uint32_t addr) {
    asm volatile("ldmatrix.sync.aligned.m8n8.x4.shared.b16 {%0,%1,%2,%3}, [%4];"
                 : "=r"(r[0]), "=r"(r[1]), "=r"(r[2]), "=r"(r[3]) : "r"(addr));
}
__device__ __forceinline__ void mma16816(float d[4], const uint32_t a[4],
                                         uint32_t b0, uint32_t b1) {
    asm("mma.sync.aligned.m16n8k16.row.col.f32.bf16.bf16.f32 "
        "{%0,%1,%2,%3}, {%4,%5,%6,%7}, {%8,%9}, {%0,%1,%2,%3};"
        : "+f"(d[0]), "+f"(d[1]), "+f"(d[2]), "+f"(d[3])
        : "r"(a[0]), "r"(a[1]), "r"(a[2]), "r"(a[3]), "r"(b0), "r"(b1));
}
__device__ __forceinline__ void cp16(uint32_t dst, const void* src) {
    asm volatile("cp.async.cg.shared.global [%0], [%1], 16;" :: "r"(dst), "l"(src) : "memory");
}
#define CP_COMMIT() asm volatile("cp.async.commit_group;" ::: "memory")
#define CP_WAIT0()  asm volatile("cp.async.wait_group 0;" ::: "memory")
#define BAR_NAMED(id, cnt) asm volatile("bar.sync %0, %1;" :: "r"(id), "r"(cnt) : "memory")

// ---------------------------------------------------------------------------
// Fused prep: z -> bf16 transposed tile + exact row norms A (strict seq).
// Block = 64 rows (one batch image slice); smem tile[c][m], pad 65.
// ---------------------------------------------------------------------------
__global__ __launch_bounds__(256)
void conv_az_kernel(const float* __restrict__ z) {
    extern __shared__ float tile[];     // [256][65] floats = 66560 B
    const int tid = threadIdx.x;
    const int n0 = blockIdx.x * 64;
    const int b = n0 >> 10, hw0 = n0 & 1023;
    const int m = tid & 63, c_lo = tid >> 6;

    // Load: coalesced over hw (m), 4 channels per iteration
    #pragma unroll 4
    for (int i = 0; i < 64; i++) {
        int c = i * 4 + c_lo;
        tile[c * 65 + m] = z[((size_t)b * CDIM + c) * 1024 + hw0 + m];
    }
    __syncthreads();

    // Write bf16 [n][c], packed pairs, coalesced over c
    __nv_bfloat162* dst = (__nv_bfloat162*)g_Abf;
    #pragma unroll
    for (int i = 0; i < 32; i++) {
        int u = i * 256 + tid;           // 0..8191
        int mm = u >> 7, c2 = u & 127;
        dst[(size_t)(n0 + mm) * 128 + c2] =
            __floats2bfloat162_rn(tile[(2 * c2) * 65 + mm], tile[(2 * c2 + 1) * 65 + mm]);
    }

    // Exact A: strict sequential fp32 chain ascending c (bit-exact emulation)
    if (tid < 64) {
        float s = 0.f;
        #pragma unroll 16
        for (int c = 0; c < CDIM; c++) {
            float v = tile[c * 65 + tid];
            s = __fadd_rn(s, __fmul_rn(v, v));
        }
        g_A[n0 + tid] = s;
    }
}

// ---------------------------------------------------------------------------
// Fused prep: emb -> bf16 + exact code norms C (strict seq).
// Block = 64 codes; smem float4 rows padded to 65 float4s.
// ---------------------------------------------------------------------------
__global__ __launch_bounds__(256)
void conv_bc_kernel(const float* __restrict__ emb) {
    extern __shared__ float4 esm[];     // [64][65] float4 = 66560 B
    float* esf = (float*)esm;
    const int tid = threadIdx.x;
    const int k0 = blockIdx.x * 64;
    const float4* src = (const float4*)(emb + (size_t)k0 * CDIM);

    #pragma unroll
    for (int i = 0; i < 16; i++) {
        int g = i * 256 + tid;           // 0..4095 float4
        int r = g >> 6, q = g & 63;
        esm[r * 65 + q] = src[g];
    }
    __syncthreads();

    // Write bf16 (same layout as emb), coalesced
    __nv_bfloat162* dst = (__nv_bfloat162*)g_Bbf;
    #pragma unroll
    for (int i = 0; i < 32; i++) {
        int u = i * 256 + tid;           // 0..8191 bf162
        int r = u >> 7, c2 = u & 127;
        dst[(size_t)(k0 + r) * 128 + c2] =
            __floats2bfloat162_rn(esf[r * 260 + 2 * c2], esf[r * 260 + 2 * c2 + 1]);
    }

    // Exact C: strict sequential chain (float4 loads, scalar order preserved)
    if (tid < 64) {
        float s = 0.f;
        #pragma unroll 8
        for (int q = 0; q < 64; q++) {
            float4 v = esm[tid * 65 + q];
            s = __fadd_rn(s, __fmul_rn(v.x, v.x));
            s = __fadd_rn(s, __fmul_rn(v.y, v.y));
            s = __fadd_rn(s, __fmul_rn(v.z, v.z));
            s = __fadd_rn(s, __fmul_rn(v.w, v.w));
        }
        g_C[k0 + tid] = s;
    }
}

// ---------------------------------------------------------------------------
// GEMM (HMMA mma.sync bf16 f32-acc) + two-pass screening, cp.async prefetch.
// 512 threads, 16 warps in 4(M) x 4(N) grid, warp tile 32x32. (R7-validated)
// ---------------------------------------------------------------------------
#define SM_A 0
#define SM_B0 65536
#define SM_B1 131072
#define SM_C  196608
#define SM_RMAX (SM_C + 1024)
#define SM_CNT  (SM_RMAX + 512)
#define SM_TOTAL (SM_CNT + 512)

__device__ __forceinline__ void cp_tile(uint32_t dst, const __nv_bfloat16* gsrc, int tid) {
    const char* src = (const char*)gsrc;
    #pragma unroll
    for (int it = 0; it < 8; it++) {
        int u = it * GTHREADS + tid;       // 0..4095 granules of 16B
        int row = u >> 5, gr = u & 31;     // 32 granules (512B) per row
        cp16(dst + row * 512 + ((gr ^ (row & 7)) << 4), src + (size_t)u * 16);
    }
}

__global__ __launch_bounds__(GTHREADS, 1)
void gemm_screen_kernel() {
    extern __shared__ char smem[];
    const uint32_t smem_base = smem_to_u32(smem);
    const int tid = threadIdx.x;
    const int wid = tid >> 5, lane = tid & 31;
    const int wm = wid & 3, wn = wid >> 2;       // 4x4 warp grid
    const int g = lane >> 2, tg = lane & 3;
    const int n0 = blockIdx.x * MT;

    float*    C_s     = (float*)(smem + SM_C);
    unsigned* sh_rmax = (unsigned*)(smem + SM_RMAX);
    int*      sh_cnt  = (int*)(smem + SM_CNT);

    if (tid < 128) { sh_rmax[tid] = f2ord(-CUDART_INF_F); sh_cnt[tid] = 0; }

    cp_tile(smem_base + SM_A, g_Abf + (size_t)n0 * CDIM, tid);
    cp_tile(smem_base + SM_B0, g_Bbf, tid);
    CP_COMMIT();
    if (tid < 128) C_s[tid] = g_C[tid];
    CP_WAIT0();
    __syncthreads();

    const uint32_t As_base = smem_base + SM_A;

    for (int i = 0; i < NCHUNKS; i++) {
        const int cur = i & 1, nxt = cur ^ 1;

        if (i + 1 < NCHUNKS) {
            cp_tile(smem_base + (nxt ? SM_B1 : SM_B0),
                    g_Bbf + (size_t)(i + 1) * NT * CDIM, tid);
            CP_COMMIT();
            if (tid < 128) C_s[nxt * 128 + tid] = g_C[(i + 1) * NT + tid];
        }

        // ---- compute chunk i: warp tile 32(M) x 32(N) ----
        const uint32_t Bs_base = smem_base + (cur ? SM_B1 : SM_B0);
        float acc[2][4][4];
        #pragma unroll
        for (int mt = 0; mt < 2; mt++)
            #pragma unroll
            for (int nt = 0; nt < 4; nt++)
                #pragma unroll
                for (int c = 0; c < 4; c++) acc[mt][nt][c] = 0.f;

        #pragma unroll
        for (int ks = 0; ks < 16; ks++) {
            uint32_t a_frag[2][4];
            #pragma unroll
            for (int mt = 0; mt < 2; mt++) {
                int row = wm * 32 + mt * 16 + (lane & 15);
                int gr  = ks * 2 + (lane >> 4);
                ldsm4(a_frag[mt], As_base + row * 512 + ((gr ^ (row & 7)) << 4));
            }
            uint32_t b_frag[2][4];
            #pragma unroll
            for (int bp = 0; bp < 2; bp++) {
                int n  = wn * 32 + bp * 16 + ((lane >> 4) << 3) + (lane & 7);
                int gr = ks * 2 + ((lane >> 3) & 1);
                ldsm4(b_frag[bp], Bs_base + n * 512 + ((gr ^ (n & 7)) << 4));
            }
            #pragma unroll
            for (int mt = 0; mt < 2; mt++)
                #pragma unroll
                for (int bp = 0; bp < 2; bp++) {
                    mma16816(acc[mt][bp * 2],     a_frag[mt], b_frag[bp][0], b_frag[bp][1]);
                    mma16816(acc[mt][bp * 2 + 1], a_frag[mt], b_frag[bp][2], b_frag[bp][3]);
                }
        }

        // ---- PASS 1: scores in-place + chunk row-max -> sh_rmax ----
        #pragma unroll
        for (int mt = 0; mt < 2; mt++) {
            float lmax[2] = {-CUDART_INF_F, -CUDART_INF_F};
            #pragma unroll
            for (int nt = 0; nt < 4; nt++)
                #pragma unroll
                for (int h = 0; h < 2; h++)
                    #pragma unroll
                    for (int q = 0; q < 2; q++) {
                        int col = wn * 32 + nt * 8 + tg * 2 + q;
                        float s = __fmaf_rn(2.0f, acc[mt][nt][h * 2 + q],
                                            -C_s[cur * 128 + col]);
                        acc[mt][nt][h * 2 + q] = s;
                        if (s > lmax[h]) lmax[h] = s;
                    }
            #pragma unroll
            for (int h = 0; h < 2; h++) {
                lmax[h] = fmaxf(lmax[h], __shfl_xor_sync(0xffffffffu, lmax[h], 1));
                lmax[h] = fmaxf(lmax[h], __shfl_xor_sync(0xffffffffu, lmax[h], 2));
                if (tg == 0) {
                    int rl = wm * 32 + mt * 16 + h * 8 + g;
                    atomicMax(&sh_rmax[rl], f2ord(lmax[h]));
                }
            }
        }
        // Rows are partitioned by wm: only the 4 wn-warps of this wm group
        // need to agree before pass 2. Named barrier, 128 threads.
        BAR_NAMED(1 + wm, 128);

        // ---- PASS 2: insert candidates above updated threshold ----
        const int k0 = i * NT;
        #pragma unroll
        for (int mt = 0; mt < 2; mt++)
            #pragma unroll
            for (int h = 0; h < 2; h++) {
                int rl = wm * 32 + mt * 16 + h * 8 + g;
                float thr = ord2f(sh_rmax[rl]) - MARGIN;
                #pragma unroll
                for (int nt = 0; nt < 4; nt++)
                    #pragma unroll
                    for (int q = 0; q < 2; q++) {
                        float s = acc[mt][nt][h * 2 + q];
                        if (s > thr) {
                            int col = wn * 32 + nt * 8 + tg * 2 + q;
                            int slot = atomicAdd(&sh_cnt[rl], 1);
                            if (slot < CAP) {
                                g_candk[(size_t)(n0 + rl) * CAP + slot] = (unsigned)(k0 + col);
                                g_cands[(size_t)(n0 + rl) * CAP + slot] = s;
                            }
                        }
                    }
            }
        if (i + 1 < NCHUNKS) CP_WAIT0();
        __syncthreads();   // buffer safety + orders pass2(i) before pass1(i+1)
    }

    if (tid < 128) {
        g_cnt[n0 + tid] = sh_cnt[tid];
        g_thresh[n0 + tid] = ord2f(sh_rmax[tid]) - MARGIN;
    }
}

// ---------------------------------------------------------------------------
// Exact reference-emulated distance (validated bit-exact in R2)
// ---------------------------------------------------------------------------
__device__ __forceinline__ float exact_d(const float* __restrict__ zp,
                                         const float* __restrict__ e,
                                         float A, float C) {
    float P = 0.f;
    #pragma unroll 16
    for (int c = 0; c < CDIM; c++)
        P = __fmaf_rn(__ldg(zp + (size_t)c * 1024), __ldg(e + c), P);
    float t = __fsub_rn(A, __fmul_rn(2.0f, P));
    return __fadd_rn(t, C);
}

__global__ __launch_bounds__(256)
void rescore_kernel(const float* __restrict__ z, const float* __restrict__ emb) {
    const int wid = threadIdx.x >> 5, lane = threadIdx.x & 31;
    const int n = blockIdx.x * 8 + wid;
    const int b = n >> 10, hw = n & 1023;
    const float* zp = z + (size_t)b * CDIM * 1024 + hw;
    const float A = g_A[n];
    const int cnt = g_cnt[n];
    const float thresh = g_thresh[n];

    float bd = CUDART_INF_F;
    int bi = 0x7fffffff;

    if (cnt <= CAP) {
        for (int base = 0; base < cnt; base += 32) {
            int l = base + lane;
            if (l < cnt) {
                float s = g_cands[(size_t)n * CAP + l];
                if (s >= thresh) {
                    int k = (int)g_candk[(size_t)n * CAP + l];
                    float d = exact_d(zp, emb + (size_t)k * CDIM, A, g_C[k]);
                    if (d < bd || (d == bd && k < bi)) { bd = d; bi = k; }
                }
            }
        }
    } else {  // overflow fallback: exact scan (safety net)
        for (int k = lane; k < KCODES; k += 32) {
            float d = exact_d(zp, emb + (size_t)k * CDIM, A, g_C[k]);
            if (d < bd || (d == bd && k < bi)) { bd = d; bi = k; }
        }
    }
    #pragma unroll
    for (int off = 16; off; off >>= 1) {
        float od = __shfl_down_sync(0xffffffffu, bd, off);
        int   oi = __shfl_down_sync(0xffffffffu, bi, off);
        if (od < bd || (od == bd && oi < bi)) { bd = od; bi = oi; }
    }
    if (lane == 0) g_idx[n] = bi;
}

// ---------------------------------------------------------------------------
// Quantize / losses / indices — emb rows staged in smem (coalesced gather)
// ---------------------------------------------------------------------------
__global__ __launch_bounds__(256)
void quantize_kernel(const float* __restrict__ z, const float* __restrict__ emb,
                     float* __restrict__ out) {
    extern __shared__ float4 eq4[];     // [64][65] float4 = 66560 B
    float* eqf = (float*)eq4;
    __shared__ int bidx_s[64];
    __shared__ float red[256];
    const int tid = threadIdx.x;
    const int n0 = blockIdx.x * 64;
    const int bimg = n0 >> 10, hw0 = n0 & 1023;
    const float* zb = z + (size_t)bimg * CDIM * 1024 + hw0;
    const size_t QELEMS = (size_t)NROWS * CDIM;

    if (tid < 64) {
        int k = g_idx[n0 + tid];
        bidx_s[tid] = k;
        out[QELEMS + 2 + n0 + tid] = (float)k;
    }
    __syncthreads();

    // Stage the 64 gathered emb rows (coalesced within each row)
    const float4* emb4 = (const float4*)emb;
    #pragma unroll
    for (int i = 0; i < 16; i++) {
        int u = i * 256 + tid;           // 0..4095 float4
        int r = u >> 6, q = u & 63;
        eq4[r * 65 + q] = emb4[(size_t)bidx_s[r] * 64 + q];
    }
    __syncthreads();

    float lsum = 0.f;
    for (int e = tid; e < 64 * CDIM; e += 256) {
        int c = e >> 6, m = e & 63;
        float qv = eqf[m * 260 + c];
        float zv = zb[(size_t)c * 1024 + m];
        float d  = __fsub_rn(qv, zv);
        out[(size_t)bimg * CDIM * 1024 + (size_t)c * 1024 + hw0 + m] = __fadd_rn(zv, d);
        lsum = __fmaf_rn(d, d, lsum);
    }
    red[tid] = lsum;
    __syncthreads();
    #pragma unroll
    for (int st = 128; st; st >>= 1) {
        if (tid < st) red[tid] += red[tid + st];
        __syncthreads();
    }
    if (tid == 0) g_partial[blockIdx.x] = red[0];
}

__global__ void finalize_kernel(float* __restrict__ out) {
    __shared__ float red[256];
    red[threadIdx.x] = g_partial[threadIdx.x];
    __syncthreads();
    #pragma unroll
    for (int st = 128; st; st >>= 1) {
        if (threadIdx.x < st) red[threadIdx.x] += red[threadIdx.x + st];
        __syncthreads();
    }
    if (threadIdx.x == 0) {
        const size_t QELEMS = (size_t)NROWS * CDIM;
        float loss = red[0] / (float)QELEMS;
        out[QELEMS]     = loss;
        out[QELEMS + 1] = 0.25f * loss;
    }
}

// ---------------------------------------------------------------------------
extern "C" void kernel_launch(void* const* d_in, const int* in_sizes, int n_in,
                              void* d_out, int out_size) {
    const float* z   = (const float*)d_in[0];
    const float* emb = (const float*)d_in[1];
    float* out = (float*)d_out;

    constexpr int PREP_SMEM = 66560;
    cudaFuncSetAttribute(gemm_screen_kernel,
                         cudaFuncAttributeMaxDynamicSharedMemorySize, SM_TOTAL);
    cudaFuncSetAttribute(conv_az_kernel,
                         cudaFuncAttributeMaxDynamicSharedMemorySize, PREP_SMEM);
    cudaFuncSetAttribute(conv_bc_kernel,
                         cudaFuncAttributeMaxDynamicSharedMemorySize, PREP_SMEM);
    cudaFuncSetAttribute(quantize_kernel,
                         cudaFuncAttributeMaxDynamicSharedMemorySize, PREP_SMEM);

    conv_az_kernel<<<NROWS / 64, 256, PREP_SMEM>>>(z);
    conv_bc_kernel<<<KCODES / 64, 256, PREP_SMEM>>>(emb);
    gemm_screen_kernel<<<NROWS / MT, GTHREADS, SM_TOTAL>>>();
    rescore_kernel<<<NROWS / 8, 256>>>(z, emb);
    quantize_kernel<<<NROWS / 64, 256, PREP_SMEM>>>(z, emb, out);
    finalize_kernel<<<1, 256>>>(out);
}

// round 12
// speedup vs baseline: 365.7307x; 1.0763x over previous
#include <cuda_runtime.h>
#include <cuda_bf16.h>
#include <cstdint>
#include <math_constants.h>

#define CDIM 256
#define KCODES 8192
#define NROWS 16384
#define NT 128              // codes per chunk
#define MT 128              // rows per CTA
#define NCHUNKS (KCODES / NT)
#define CAP 128             // candidate slots per row
#define MARGIN 1.0e-3f
#define GTHREADS 512

// ---------------------------------------------------------------------------
// Device globals (allocation-free scratch)
// ---------------------------------------------------------------------------
__device__ __align__(16) __nv_bfloat16 g_Abf[(size_t)NROWS * CDIM];   // [n][c]
__device__ __align__(16) __nv_bfloat16 g_Bbf[(size_t)KCODES * CDIM];  // [k][c]
__device__ float    g_A[NROWS];                          // exact ||x||^2 (strict seq)
__device__ float    g_C[KCODES];                         // exact ||e||^2 (strict seq)
__device__ unsigned g_candk[(size_t)NROWS * CAP];
__device__ float    g_cands[(size_t)NROWS * CAP];
__device__ int      g_cnt[NROWS];
__device__ float    g_thresh[NROWS];
__device__ int      g_idx[NROWS];
__device__ float    g_partial[NROWS / 64];

// ---------------------------------------------------------------------------
// Helpers
// ---------------------------------------------------------------------------
__device__ __forceinline__ uint32_t smem_to_u32(const void* p) {
    uint32_t a;
    asm("{ .reg .u64 t; cvta.to.shared.u64 t, %1; cvt.u32.u64 %0, t; }" : "=r"(a) : "l"(p));
    return a;
}
__device__ __forceinline__ unsigned f2ord(float f) {
    unsigned u = __float_as_uint(f);
    return (u & 0x80000000u) ? ~u : (u | 0x80000000u);
}
__device__ __forceinline__ float ord2f(unsigned u) {
    return __uint_as_float((u & 0x80000000u) ? (u ^ 0x80000000u) : ~u);
}
__device__ __forceinline__ void ldsm4(uint32_t r[4], uint32_t addr) {
    asm volatile("ldmatrix.sync.aligned.m8n8.x4.shared.b16 {%0,%1,%2,%3}, [%4];"
                 : "=r"(r[0]), "=r"(r[1]), "=r"(r[2]), "=r"(r[3]) : "r"(addr));
}
__device__ __forceinline__ void mma16816(float d[4], const uint32_t a[4],
                                         uint32_t b0, uint32_t b1) {
    asm("mma.sync.aligned.m16n8k16.row.col.f32.bf16.bf16.f32 "
        "{%0,%1,%2,%3}, {%4,%5,%6,%7}, {%8,%9}, {%0,%1,%2,%3};"
        : "+f"(d[0]), "+f"(d[1]), "+f"(d[2]), "+f"(d[3])
        : "r"(a[0]), "r"(a[1]), "r"(a[2]), "r"(a[3]), "r"(b0), "r"(b1));
}
__device__ __forceinline__ void cp16(uint32_t dst, const void* src) {
    asm volatile("cp.async.cg.shared.global [%0], [%1], 16;" :: "r"(dst), "l"(src) : "memory");
}
#define CP_COMMIT() asm volatile("cp.async.commit_group;" ::: "memory")
#define CP_WAIT0()  asm volatile("cp.async.wait_group 0;" ::: "memory")
#define BAR_NAMED(id, cnt) asm volatile("bar.sync %0, %1;" :: "r"(id), "r"(cnt) : "memory")

// ---------------------------------------------------------------------------
// Fused prep: z -> bf16 transposed tile + exact row norms A (strict seq).
// ---------------------------------------------------------------------------
__global__ __launch_bounds__(256)
void conv_az_kernel(const float* __restrict__ z) {
    extern __shared__ float tile[];     // [256][65] floats = 66560 B
    const int tid = threadIdx.x;
    const int n0 = blockIdx.x * 64;
    const int b = n0 >> 10, hw0 = n0 & 1023;
    const int m = tid & 63, c_lo = tid >> 6;

    #pragma unroll 4
    for (int i = 0; i < 64; i++) {
        int c = i * 4 + c_lo;
        tile[c * 65 + m] = z[((size_t)b * CDIM + c) * 1024 + hw0 + m];
    }
    __syncthreads();

    __nv_bfloat162* dst = (__nv_bfloat162*)g_Abf;
    #pragma unroll
    for (int i = 0; i < 32; i++) {
        int u = i * 256 + tid;
        int mm = u >> 7, c2 = u & 127;
        dst[(size_t)(n0 + mm) * 128 + c2] =
            __floats2bfloat162_rn(tile[(2 * c2) * 65 + mm], tile[(2 * c2 + 1) * 65 + mm]);
    }

    if (tid < 64) {
        float s = 0.f;
        #pragma unroll 16
        for (int c = 0; c < CDIM; c++) {
            float v = tile[c * 65 + tid];
            s = __fadd_rn(s, __fmul_rn(v, v));
        }
        g_A[n0 + tid] = s;
    }
}

// ---------------------------------------------------------------------------
// Fused prep: emb -> bf16 + exact code norms C (strict seq).
// ---------------------------------------------------------------------------
__global__ __launch_bounds__(256)
void conv_bc_kernel(const float* __restrict__ emb) {
    extern __shared__ float4 esm[];     // [64][65] float4 = 66560 B
    float* esf = (float*)esm;
    const int tid = threadIdx.x;
    const int k0 = blockIdx.x * 64;
    const float4* src = (const float4*)(emb + (size_t)k0 * CDIM);

    #pragma unroll
    for (int i = 0; i < 16; i++) {
        int g = i * 256 + tid;
        int r = g >> 6, q = g & 63;
        esm[r * 65 + q] = src[g];
    }
    __syncthreads();

    __nv_bfloat162* dst = (__nv_bfloat162*)g_Bbf;
    #pragma unroll
    for (int i = 0; i < 32; i++) {
        int u = i * 256 + tid;
        int r = u >> 7, c2 = u & 127;
        dst[(size_t)(k0 + r) * 128 + c2] =
            __floats2bfloat162_rn(esf[r * 260 + 2 * c2], esf[r * 260 + 2 * c2 + 1]);
    }

    if (tid < 64) {
        float s = 0.f;
        #pragma unroll 8
        for (int q = 0; q < 64; q++) {
            float4 v = esm[tid * 65 + q];
            s = __fadd_rn(s, __fmul_rn(v.x, v.x));
            s = __fadd_rn(s, __fmul_rn(v.y, v.y));
            s = __fadd_rn(s, __fmul_rn(v.z, v.z));
            s = __fadd_rn(s, __fmul_rn(v.w, v.w));
        }
        g_C[k0 + tid] = s;
    }
}

// ---------------------------------------------------------------------------
// GEMM (HMMA mma.sync bf16 f32-acc) + two-pass screening (R7/R11-validated)
// ---------------------------------------------------------------------------
#define SM_A 0
#define SM_B0 65536
#define SM_B1 131072
#define SM_C  196608
#define SM_RMAX (SM_C + 1024)
#define SM_CNT  (SM_RMAX + 512)
#define SM_TOTAL (SM_CNT + 512)

__device__ __forceinline__ void cp_tile(uint32_t dst, const __nv_bfloat16* gsrc, int tid) {
    const char* src = (const char*)gsrc;
    #pragma unroll
    for (int it = 0; it < 8; it++) {
        int u = it * GTHREADS + tid;
        int row = u >> 5, gr = u & 31;
        cp16(dst + row * 512 + ((gr ^ (row & 7)) << 4), src + (size_t)u * 16);
    }
}

__global__ __launch_bounds__(GTHREADS, 1)
void gemm_screen_kernel() {
    extern __shared__ char smem[];
    const uint32_t smem_base = smem_to_u32(smem);
    const int tid = threadIdx.x;
    const int wid = tid >> 5, lane = tid & 31;
    const int wm = wid & 3, wn = wid >> 2;
    const int g = lane >> 2, tg = lane & 3;
    const int n0 = blockIdx.x * MT;

    float*    C_s     = (float*)(smem + SM_C);
    unsigned* sh_rmax = (unsigned*)(smem + SM_RMAX);
    int*      sh_cnt  = (int*)(smem + SM_CNT);

    if (tid < 128) { sh_rmax[tid] = f2ord(-CUDART_INF_F); sh_cnt[tid] = 0; }

    cp_tile(smem_base + SM_A, g_Abf + (size_t)n0 * CDIM, tid);
    cp_tile(smem_base + SM_B0, g_Bbf, tid);
    CP_COMMIT();
    if (tid < 128) C_s[tid] = g_C[tid];
    CP_WAIT0();
    __syncthreads();

    const uint32_t As_base = smem_base + SM_A;

    for (int i = 0; i < NCHUNKS; i++) {
        const int cur = i & 1, nxt = cur ^ 1;

        if (i + 1 < NCHUNKS) {
            cp_tile(smem_base + (nxt ? SM_B1 : SM_B0),
                    g_Bbf + (size_t)(i + 1) * NT * CDIM, tid);
            CP_COMMIT();
            if (tid < 128) C_s[nxt * 128 + tid] = g_C[(i + 1) * NT + tid];
        }

        const uint32_t Bs_base = smem_base + (cur ? SM_B1 : SM_B0);
        float acc[2][4][4];
        #pragma unroll
        for (int mt = 0; mt < 2; mt++)
            #pragma unroll
            for (int nt = 0; nt < 4; nt++)
                #pragma unroll
                for (int c = 0; c < 4; c++) acc[mt][nt][c] = 0.f;

        #pragma unroll
        for (int ks = 0; ks < 16; ks++) {
            uint32_t a_frag[2][4];
            #pragma unroll
            for (int mt = 0; mt < 2; mt++) {
                int row = wm * 32 + mt * 16 + (lane & 15);
                int gr  = ks * 2 + (lane >> 4);
                ldsm4(a_frag[mt], As_base + row * 512 + ((gr ^ (row & 7)) << 4));
            }
            uint32_t b_frag[2][4];
            #pragma unroll
            for (int bp = 0; bp < 2; bp++) {
                int n  = wn * 32 + bp * 16 + ((lane >> 4) << 3) + (lane & 7);
                int gr = ks * 2 + ((lane >> 3) & 1);
                ldsm4(b_frag[bp], Bs_base + n * 512 + ((gr ^ (n & 7)) << 4));
            }
            #pragma unroll
            for (int mt = 0; mt < 2; mt++)
                #pragma unroll
                for (int bp = 0; bp < 2; bp++) {
                    mma16816(acc[mt][bp * 2],     a_frag[mt], b_frag[bp][0], b_frag[bp][1]);
                    mma16816(acc[mt][bp * 2 + 1], a_frag[mt], b_frag[bp][2], b_frag[bp][3]);
                }
        }

        // PASS 1: scores in-place + chunk row-max
        #pragma unroll
        for (int mt = 0; mt < 2; mt++) {
            float lmax[2] = {-CUDART_INF_F, -CUDART_INF_F};
            #pragma unroll
            for (int nt = 0; nt < 4; nt++)
                #pragma unroll
                for (int h = 0; h < 2; h++)
                    #pragma unroll
                    for (int q = 0; q < 2; q++) {
                        int col = wn * 32 + nt * 8 + tg * 2 + q;
                        float s = __fmaf_rn(2.0f, acc[mt][nt][h * 2 + q],
                                            -C_s[cur * 128 + col]);
                        acc[mt][nt][h * 2 + q] = s;
                        if (s > lmax[h]) lmax[h] = s;
                    }
            #pragma unroll
            for (int h = 0; h < 2; h++) {
                lmax[h] = fmaxf(lmax[h], __shfl_xor_sync(0xffffffffu, lmax[h], 1));
                lmax[h] = fmaxf(lmax[h], __shfl_xor_sync(0xffffffffu, lmax[h], 2));
                if (tg == 0) {
                    int rl = wm * 32 + mt * 16 + h * 8 + g;
                    atomicMax(&sh_rmax[rl], f2ord(lmax[h]));
                }
            }
        }
        BAR_NAMED(1 + wm, 128);   // only the 4 wn-warps sharing rows must agree

        // PASS 2: insert candidates above updated threshold
        const int k0 = i * NT;
        #pragma unroll
        for (int mt = 0; mt < 2; mt++)
            #pragma unroll
            for (int h = 0; h < 2; h++) {
                int rl = wm * 32 + mt * 16 + h * 8 + g;
                float thr = ord2f(sh_rmax[rl]) - MARGIN;
                #pragma unroll
                for (int nt = 0; nt < 4; nt++)
                    #pragma unroll
                    for (int q = 0; q < 2; q++) {
                        float s = acc[mt][nt][h * 2 + q];
                        if (s > thr) {
                            int col = wn * 32 + nt * 8 + tg * 2 + q;
                            int slot = atomicAdd(&sh_cnt[rl], 1);
                            if (slot < CAP) {
                                g_candk[(size_t)(n0 + rl) * CAP + slot] = (unsigned)(k0 + col);
                                g_cands[(size_t)(n0 + rl) * CAP + slot] = s;
                            }
                        }
                    }
            }
        if (i + 1 < NCHUNKS) CP_WAIT0();
        __syncthreads();
    }

    if (tid < 128) {
        g_cnt[n0 + tid] = sh_cnt[tid];
        g_thresh[n0 + tid] = ord2f(sh_rmax[tid]) - MARGIN;
    }
}

// ---------------------------------------------------------------------------
// Exact reference-emulated distance, thread-per-row variant.
// Same sequential fp32 fma chain ascending c (bit-exact, R2-validated order);
// only load WIDTH changes: float4 emb loads, 16-wide batched z loads.
// ---------------------------------------------------------------------------
__device__ __forceinline__ float exact_d_t(const float* __restrict__ zp,
                                           const float4* __restrict__ e4,
                                           float A, float C) {
    float P = 0.f;
    #pragma unroll
    for (int c0 = 0; c0 < CDIM; c0 += 16) {
        float zv[16];
        #pragma unroll
        for (int u = 0; u < 16; u++) zv[u] = __ldg(zp + (size_t)(c0 + u) * 1024);
        float4 ev[4];
        #pragma unroll
        for (int u = 0; u < 4; u++) ev[u] = __ldg(e4 + (c0 >> 2) + u);
        #pragma unroll
        for (int u = 0; u < 4; u++) {
            P = __fmaf_rn(zv[4 * u + 0], ev[u].x, P);
            P = __fmaf_rn(zv[4 * u + 1], ev[u].y, P);
            P = __fmaf_rn(zv[4 * u + 2], ev[u].z, P);
            P = __fmaf_rn(zv[4 * u + 3], ev[u].w, P);
        }
    }
    float t = __fsub_rn(A, __fmul_rn(2.0f, P));
    return __fadd_rn(t, C);
}

// One THREAD per row: exact argmin (first-index tie-break) over candidates.
// Lanes hold consecutive rows -> z loads coalesce across the warp.
__global__ __launch_bounds__(64)
void rescore_kernel(const float* __restrict__ z, const float* __restrict__ emb) {
    const int n = blockIdx.x * 64 + threadIdx.x;
    const int b = n >> 10, hw = n & 1023;
    const float* zp = z + (size_t)b * CDIM * 1024 + hw;
    const float A = g_A[n];
    const int cnt = g_cnt[n];
    const float thresh = g_thresh[n];

    float bd = CUDART_INF_F;
    int bi = 0x7fffffff;

    if (cnt <= CAP) {
        for (int l = 0; l < cnt; l++) {
            float s = g_cands[(size_t)n * CAP + l];
            if (s >= thresh) {
                int k = (int)g_candk[(size_t)n * CAP + l];
                float d = exact_d_t(zp, (const float4*)(emb + (size_t)k * CDIM), A, g_C[k]);
                if (d < bd || (d == bd && k < bi)) { bd = d; bi = k; }
            }
        }
    } else {  // overflow fallback: exact scan of all codes (never fires; safety)
        for (int k = 0; k < KCODES; k++) {
            float d = exact_d_t(zp, (const float4*)(emb + (size_t)k * CDIM), A, g_C[k]);
            if (d < bd) { bd = d; bi = k; }   // ascending k: first-min kept
        }
    }
    g_idx[n] = bi;
}

// ---------------------------------------------------------------------------
// Quantize / losses / indices — emb rows staged in smem (coalesced gather)
// ---------------------------------------------------------------------------
__global__ __launch_bounds__(256)
void quantize_kernel(const float* __restrict__ z, const float* __restrict__ emb,
                     float* __restrict__ out) {
    extern __shared__ float4 eq4[];     // [64][65] float4 = 66560 B
    float* eqf = (float*)eq4;
    __shared__ int bidx_s[64];
    __shared__ float red[256];
    const int tid = threadIdx.x;
    const int n0 = blockIdx.x * 64;
    const int bimg = n0 >> 10, hw0 = n0 & 1023;
    const float* zb = z + (size_t)bimg * CDIM * 1024 + hw0;
    const size_t QELEMS = (size_t)NROWS * CDIM;

    if (tid < 64) {
        int k = g_idx[n0 + tid];
        bidx_s[tid] = k;
        out[QELEMS + 2 + n0 + tid] = (float)k;
    }
    __syncthreads();

    const float4* emb4 = (const float4*)emb;
    #pragma unroll
    for (int i = 0; i < 16; i++) {
        int u = i * 256 + tid;
        int r = u >> 6, q = u & 63;
        eq4[r * 65 + q] = emb4[(size_t)bidx_s[r] * 64 + q];
    }
    __syncthreads();

    float lsum = 0.f;
    for (int e = tid; e < 64 * CDIM; e += 256) {
        int c = e >> 6, m = e & 63;
        float qv = eqf[m * 260 + c];
        float zv = zb[(size_t)c * 1024 + m];
        float d  = __fsub_rn(qv, zv);
        out[(size_t)bimg * CDIM * 1024 + (size_t)c * 1024 + hw0 + m] = __fadd_rn(zv, d);
        lsum = __fmaf_rn(d, d, lsum);
    }
    red[tid] = lsum;
    __syncthreads();
    #pragma unroll
    for (int st = 128; st; st >>= 1) {
        if (tid < st) red[tid] += red[tid + st];
        __syncthreads();
    }
    if (tid == 0) g_partial[blockIdx.x] = red[0];
}

__global__ void finalize_kernel(float* __restrict__ out) {
    __shared__ float red[256];
    red[threadIdx.x] = g_partial[threadIdx.x];
    __syncthreads();
    #pragma unroll
    for (int st = 128; st; st >>= 1) {
        if (threadIdx.x < st) red[threadIdx.x] += red[threadIdx.x + st];
        __syncthreads();
    }
    if (threadIdx.x == 0) {
        const size_t QELEMS = (size_t)NROWS * CDIM;
        float loss = red[0] / (float)QELEMS;
        out[QELEMS]     = loss;
        out[QELEMS + 1] = 0.25f * loss;
    }
}

// ---------------------------------------------------------------------------
extern "C" void kernel_launch(void* const* d_in, const int* in_sizes, int n_in,
                              void* d_out, int out_size) {
    const float* z   = (const float*)d_in[0];
    const float* emb = (const float*)d_in[1];
    float* out = (float*)d_out;

    constexpr int PREP_SMEM = 66560;
    cudaFuncSetAttribute(gemm_screen_kernel,
                         cudaFuncAttributeMaxDynamicSharedMemorySize, SM_TOTAL);
    cudaFuncSetAttribute(conv_az_kernel,
                         cudaFuncAttributeMaxDynamicSharedMemorySize, PREP_SMEM);
    cudaFuncSetAttribute(conv_bc_kernel,
                         cudaFuncAttributeMaxDynamicSharedMemorySize, PREP_SMEM);
    cudaFuncSetAttribute(quantize_kernel,
                         cudaFuncAttributeMaxDynamicSharedMemorySize, PREP_SMEM);

    conv_az_kernel<<<NROWS / 64, 256, PREP_SMEM>>>(z);
    conv_bc_kernel<<<KCODES / 64, 256, PREP_SMEM>>>(emb);
    gemm_screen_kernel<<<NROWS / MT, GTHREADS, SM_TOTAL>>>();
    rescore_kernel<<<NROWS / 64, 64>>>(z, emb);
    quantize_kernel<<<NROWS / 64, 256, PREP_SMEM>>>(z, emb, out);
    finalize_kernel<<<1, 256>>>(out);
}

// round 13
// speedup vs baseline: 367.1472x; 1.0039x over previous
#include <cuda_runtime.h>
#include <cuda_bf16.h>
#include <cstdint>
#include <math_constants.h>

#define CDIM 256
#define KCODES 8192
#define NROWS 16384
#define NT 128              // codes per chunk
#define MT 128              // rows per CTA
#define NCHUNKS (KCODES / NT)
#define CAP 128             // candidate slots per row
#define MARGIN 1.0e-3f
#define GTHREADS 512

// ---------------------------------------------------------------------------
// Device globals (allocation-free scratch)
// ---------------------------------------------------------------------------
__device__ __align__(16) __nv_bfloat16 g_Abf[(size_t)NROWS * CDIM];   // [n][c]
__device__ __align__(16) __nv_bfloat16 g_Bbf[(size_t)KCODES * CDIM];  // [k][c]
__device__ float    g_A[NROWS];                          // exact ||x||^2 (strict seq)
__device__ float    g_C[KCODES];                         // exact ||e||^2 (strict seq)
__device__ unsigned g_candk[(size_t)NROWS * CAP];
__device__ float    g_cands[(size_t)NROWS * CAP];
__device__ int      g_cnt[NROWS];
__device__ float    g_thresh[NROWS];
__device__ int      g_idx[NROWS];
__device__ float    g_partial[NROWS / 64];

// ---------------------------------------------------------------------------
// Helpers
// ---------------------------------------------------------------------------
__device__ __forceinline__ uint32_t smem_to_u32(const void* p) {
    uint32_t a;
    asm("{ .reg .u64 t; cvta.to.shared.u64 t, %1; cvt.u32.u64 %0, t; }" : "=r"(a) : "l"(p));
    return a;
}
__device__ __forceinline__ unsigned f2ord(float f) {
    unsigned u = __float_as_uint(f);
    return (u & 0x80000000u) ? ~u : (u | 0x80000000u);
}
__device__ __forceinline__ float ord2f(unsigned u) {
    return __uint_as_float((u & 0x80000000u) ? (u ^ 0x80000000u) : ~u);
}
__device__ __forceinline__ void ldsm4(uint32_t r[4], uint32_t addr) {
    asm volatile("ldmatrix.sync.aligned.m8n8.x4.shared.b16 {%0,%1,%2,%3}, [%4];"
                 : "=r"(r[0]), "=r"(r[1]), "=r"(r[2]), "=r"(r[3]) : "r"(addr));
}
__device__ __forceinline__ void mma16816(float d[4], const uint32_t a[4],
                                         uint32_t b0, uint32_t b1) {
    asm("mma.sync.aligned.m16n8k16.row.col.f32.bf16.bf16.f32 "
        "{%0,%1,%2,%3}, {%4,%5,%6,%7}, {%8,%9}, {%0,%1,%2,%3};"
        : "+f"(d[0]), "+f"(d[1]), "+f"(d[2]), "+f"(d[3])
        : "r"(a[0]), "r"(a[1]), "r"(a[2]), "r"(a[3]), "r"(b0), "r"(b1));
}
__device__ __forceinline__ void cp16(uint32_t dst, const void* src) {
    asm volatile("cp.async.cg.shared.global [%0], [%1], 16;" :: "r"(dst), "l"(src) : "memory");
}
#define CP_COMMIT() asm volatile("cp.async.commit_group;" ::: "memory")
#define CP_WAIT0()  asm volatile("cp.async.wait_group 0;" ::: "memory")
#define BAR_NAMED(id, cnt) asm volatile("bar.sync %0, %1;" :: "r"(id), "r"(cnt) : "memory")

// ---------------------------------------------------------------------------
// Fused prep: z -> bf16 transposed tile + exact row norms A (strict seq).
// ---------------------------------------------------------------------------
__global__ __launch_bounds__(256)
void conv_az_kernel(const float* __restrict__ z) {
    extern __shared__ float tile[];     // [256][65] floats = 66560 B
    const int tid = threadIdx.x;
    const int n0 = blockIdx.x * 64;
    const int b = n0 >> 10, hw0 = n0 & 1023;
    const int m = tid & 63, c_lo = tid >> 6;

    #pragma unroll 4
    for (int i = 0; i < 64; i++) {
        int c = i * 4 + c_lo;
        tile[c * 65 + m] = z[((size_t)b * CDIM + c) * 1024 + hw0 + m];
    }
    __syncthreads();

    __nv_bfloat162* dst = (__nv_bfloat162*)g_Abf;
    #pragma unroll
    for (int i = 0; i < 32; i++) {
        int u = i * 256 + tid;
        int mm = u >> 7, c2 = u & 127;
        dst[(size_t)(n0 + mm) * 128 + c2] =
            __floats2bfloat162_rn(tile[(2 * c2) * 65 + mm], tile[(2 * c2 + 1) * 65 + mm]);
    }

    if (tid < 64) {
        float s = 0.f;
        #pragma unroll 16
        for (int c = 0; c < CDIM; c++) {
            float v = tile[c * 65 + tid];
            s = __fadd_rn(s, __fmul_rn(v, v));
        }
        g_A[n0 + tid] = s;
    }
}

// ---------------------------------------------------------------------------
// Fused prep: emb -> bf16 + exact code norms C (strict seq).
// ---------------------------------------------------------------------------
__global__ __launch_bounds__(256)
void conv_bc_kernel(const float* __restrict__ emb) {
    extern __shared__ float4 esm[];     // [64][65] float4 = 66560 B
    float* esf = (float*)esm;
    const int tid = threadIdx.x;
    const int k0 = blockIdx.x * 64;
    const float4* src = (const float4*)(emb + (size_t)k0 * CDIM);

    #pragma unroll
    for (int i = 0; i < 16; i++) {
        int g = i * 256 + tid;
        int r = g >> 6, q = g & 63;
        esm[r * 65 + q] = src[g];
    }
    __syncthreads();

    __nv_bfloat162* dst = (__nv_bfloat162*)g_Bbf;
    #pragma unroll
    for (int i = 0; i < 32; i++) {
        int u = i * 256 + tid;
        int r = u >> 7, c2 = u & 127;
        dst[(size_t)(k0 + r) * 128 + c2] =
            __floats2bfloat162_rn(esf[r * 260 + 2 * c2], esf[r * 260 + 2 * c2 + 1]);
    }

    if (tid < 64) {
        float s = 0.f;
        #pragma unroll 8
        for (int q = 0; q < 64; q++) {
            float4 v = esm[tid * 65 + q];
            s = __fadd_rn(s, __fmul_rn(v.x, v.x));
            s = __fadd_rn(s, __fmul_rn(v.y, v.y));
            s = __fadd_rn(s, __fmul_rn(v.z, v.z));
            s = __fadd_rn(s, __fmul_rn(v.w, v.w));
        }
        g_C[k0 + tid] = s;
    }
}

// ---------------------------------------------------------------------------
// GEMM (HMMA mma.sync bf16 f32-acc) + two-pass screening (R7/R11-validated)
// ---------------------------------------------------------------------------
#define SM_A 0
#define SM_B0 65536
#define SM_B1 131072
#define SM_C  196608
#define SM_RMAX (SM_C + 1024)
#define SM_CNT  (SM_RMAX + 512)
#define SM_TOTAL (SM_CNT + 512)

__device__ __forceinline__ void cp_tile(uint32_t dst, const __nv_bfloat16* gsrc, int tid) {
    const char* src = (const char*)gsrc;
    #pragma unroll
    for (int it = 0; it < 8; it++) {
        int u = it * GTHREADS + tid;
        int row = u >> 5, gr = u & 31;
        cp16(dst + row * 512 + ((gr ^ (row & 7)) << 4), src + (size_t)u * 16);
    }
}

__global__ __launch_bounds__(GTHREADS, 1)
void gemm_screen_kernel() {
    extern __shared__ char smem[];
    const uint32_t smem_base = smem_to_u32(smem);
    const int tid = threadIdx.x;
    const int wid = tid >> 5, lane = tid & 31;
    const int wm = wid & 3, wn = wid >> 2;
    const int g = lane >> 2, tg = lane & 3;
    const int n0 = blockIdx.x * MT;

    float*    C_s     = (float*)(smem + SM_C);
    unsigned* sh_rmax = (unsigned*)(smem + SM_RMAX);
    int*      sh_cnt  = (int*)(smem + SM_CNT);

    if (tid < 128) { sh_rmax[tid] = f2ord(-CUDART_INF_F); sh_cnt[tid] = 0; }

    cp_tile(smem_base + SM_A, g_Abf + (size_t)n0 * CDIM, tid);
    cp_tile(smem_base + SM_B0, g_Bbf, tid);
    CP_COMMIT();
    if (tid < 128) C_s[tid] = g_C[tid];
    CP_WAIT0();
    __syncthreads();

    const uint32_t As_base = smem_base + SM_A;

    for (int i = 0; i < NCHUNKS; i++) {
        const int cur = i & 1, nxt = cur ^ 1;

        if (i + 1 < NCHUNKS) {
            cp_tile(smem_base + (nxt ? SM_B1 : SM_B0),
                    g_Bbf + (size_t)(i + 1) * NT * CDIM, tid);
            CP_COMMIT();
            if (tid < 128) C_s[nxt * 128 + tid] = g_C[(i + 1) * NT + tid];
        }

        const uint32_t Bs_base = smem_base + (cur ? SM_B1 : SM_B0);
        float acc[2][4][4];
        #pragma unroll
        for (int mt = 0; mt < 2; mt++)
            #pragma unroll
            for (int nt = 0; nt < 4; nt++)
                #pragma unroll
                for (int c = 0; c < 4; c++) acc[mt][nt][c] = 0.f;

        #pragma unroll
        for (int ks = 0; ks < 16; ks++) {
            uint32_t a_frag[2][4];
            #pragma unroll
            for (int mt = 0; mt < 2; mt++) {
                int row = wm * 32 + mt * 16 + (lane & 15);
                int gr  = ks * 2 + (lane >> 4);
                ldsm4(a_frag[mt], As_base + row * 512 + ((gr ^ (row & 7)) << 4));
            }
            uint32_t b_frag[2][4];
            #pragma unroll
            for (int bp = 0; bp < 2; bp++) {
                int n  = wn * 32 + bp * 16 + ((lane >> 4) << 3) + (lane & 7);
                int gr = ks * 2 + ((lane >> 3) & 1);
                ldsm4(b_frag[bp], Bs_base + n * 512 + ((gr ^ (n & 7)) << 4));
            }
            #pragma unroll
            for (int mt = 0; mt < 2; mt++)
                #pragma unroll
                for (int bp = 0; bp < 2; bp++) {
                    mma16816(acc[mt][bp * 2],     a_frag[mt], b_frag[bp][0], b_frag[bp][1]);
                    mma16816(acc[mt][bp * 2 + 1], a_frag[mt], b_frag[bp][2], b_frag[bp][3]);
                }
        }

        // PASS 1: scores in-place + chunk row-max
        #pragma unroll
        for (int mt = 0; mt < 2; mt++) {
            float lmax[2] = {-CUDART_INF_F, -CUDART_INF_F};
            #pragma unroll
            for (int nt = 0; nt < 4; nt++)
                #pragma unroll
                for (int h = 0; h < 2; h++)
                    #pragma unroll
                    for (int q = 0; q < 2; q++) {
                        int col = wn * 32 + nt * 8 + tg * 2 + q;
                        float s = __fmaf_rn(2.0f, acc[mt][nt][h * 2 + q],
                                            -C_s[cur * 128 + col]);
                        acc[mt][nt][h * 2 + q] = s;
                        if (s > lmax[h]) lmax[h] = s;
                    }
            #pragma unroll
            for (int h = 0; h < 2; h++) {
                lmax[h] = fmaxf(lmax[h], __shfl_xor_sync(0xffffffffu, lmax[h], 1));
                lmax[h] = fmaxf(lmax[h], __shfl_xor_sync(0xffffffffu, lmax[h], 2));
                if (tg == 0) {
                    int rl = wm * 32 + mt * 16 + h * 8 + g;
                    atomicMax(&sh_rmax[rl], f2ord(lmax[h]));
                }
            }
        }
        BAR_NAMED(1 + wm, 128);   // only the 4 wn-warps sharing rows must agree

        // PASS 2: insert candidates above updated threshold
        const int k0 = i * NT;
        #pragma unroll
        for (int mt = 0; mt < 2; mt++)
            #pragma unroll
            for (int h = 0; h < 2; h++) {
                int rl = wm * 32 + mt * 16 + h * 8 + g;
                float thr = ord2f(sh_rmax[rl]) - MARGIN;
                #pragma unroll
                for (int nt = 0; nt < 4; nt++)
                    #pragma unroll
                    for (int q = 0; q < 2; q++) {
                        float s = acc[mt][nt][h * 2 + q];
                        if (s > thr) {
                            int col = wn * 32 + nt * 8 + tg * 2 + q;
                            int slot = atomicAdd(&sh_cnt[rl], 1);
                            if (slot < CAP) {
                                g_candk[(size_t)(n0 + rl) * CAP + slot] = (unsigned)(k0 + col);
                                g_cands[(size_t)(n0 + rl) * CAP + slot] = s;
                            }
                        }
                    }
            }
        if (i + 1 < NCHUNKS) CP_WAIT0();
        __syncthreads();
    }

    if (tid < 128) {
        g_cnt[n0 + tid] = sh_cnt[tid];
        g_thresh[n0 + tid] = ord2f(sh_rmax[tid]) - MARGIN;
    }
}

// ---------------------------------------------------------------------------
// Rescore v3: 256 threads / 64 rows, z tile staged in smem, 4 threads per row
// split the candidate slots. Exact fp32 chain ascending c (bit-exact order);
// z reads come from smem (LDS, conflict-free: stride 65, lanes differ in m).
// ---------------------------------------------------------------------------
__device__ __forceinline__ float exact_d_s(const float* __restrict__ zrow,
                                           const float4* __restrict__ e4,
                                           float A, float C) {
    float P = 0.f;
    #pragma unroll
    for (int c0 = 0; c0 < CDIM; c0 += 16) {
        float4 ev[4];
        #pragma unroll
        for (int u = 0; u < 4; u++) ev[u] = __ldg(e4 + (c0 >> 2) + u);
        #pragma unroll
        for (int u = 0; u < 4; u++) {
            P = __fmaf_rn(zrow[(c0 + 4 * u + 0) * 65], ev[u].x, P);
            P = __fmaf_rn(zrow[(c0 + 4 * u + 1) * 65], ev[u].y, P);
            P = __fmaf_rn(zrow[(c0 + 4 * u + 2) * 65], ev[u].z, P);
            P = __fmaf_rn(zrow[(c0 + 4 * u + 3) * 65], ev[u].w, P);
        }
    }
    float t = __fsub_rn(A, __fmul_rn(2.0f, P));
    return __fadd_rn(t, C);
}

__global__ __launch_bounds__(256)
void rescore_kernel(const float* __restrict__ z, const float* __restrict__ emb) {
    extern __shared__ float rsm[];           // tile [256][65] + bd[256] + bi[256]
    float* tile = rsm;                        // 66560 B
    float* s_bd = rsm + 256 * 65;             // 1024 B
    int*   s_bi = (int*)(s_bd + 256);         // 1024 B

    const int tid = threadIdx.x;
    const int n0 = blockIdx.x * 64;
    const int b = n0 >> 10, hw0 = n0 & 1023;

    // Stage z tile [c][m], coalesced over m (same pattern as conv_az)
    {
        const int m = tid & 63, c_lo = tid >> 6;
        #pragma unroll 4
        for (int i = 0; i < 64; i++) {
            int c = i * 4 + c_lo;
            tile[c * 65 + m] = z[((size_t)b * CDIM + c) * 1024 + hw0 + m];
        }
    }
    __syncthreads();

    const int m = tid & 63;                  // row within block
    const int part = tid >> 6;               // 0..3 candidate partition
    const int n = n0 + m;
    const float A = g_A[n];
    const int cnt = g_cnt[n];
    const float thresh = g_thresh[n];
    const float* zrow = tile + m;

    float bd = CUDART_INF_F;
    int bi = 0x7fffffff;

    if (cnt <= CAP) {
        for (int l = part; l < cnt; l += 4) {
            float s = g_cands[(size_t)n * CAP + l];
            if (s >= thresh) {
                int k = (int)g_candk[(size_t)n * CAP + l];
                float d = exact_d_s(zrow, (const float4*)(emb + (size_t)k * CDIM),
                                    A, g_C[k]);
                if (d < bd || (d == bd && k < bi)) { bd = d; bi = k; }
            }
        }
    } else {  // overflow fallback (never fires; safety): split full scan 4-way
        for (int k = part; k < KCODES; k += 4) {
            float d = exact_d_s(zrow, (const float4*)(emb + (size_t)k * CDIM),
                                A, g_C[k]);
            if (d < bd || (d == bd && k < bi)) { bd = d; bi = k; }
        }
    }
    s_bd[tid] = bd;
    s_bi[tid] = bi;
    __syncthreads();

    // Merge the 4 partitions in fixed order (deterministic total order on (d,k))
    if (tid < 64) {
        float fbd = s_bd[tid];
        int   fbi = s_bi[tid];
        #pragma unroll
        for (int j = 1; j < 4; j++) {
            float od = s_bd[tid + j * 64];
            int   oi = s_bi[tid + j * 64];
            if (od < fbd || (od == fbd && oi < fbi)) { fbd = od; fbi = oi; }
        }
        g_idx[n0 + tid] = fbi;
    }
}

// ---------------------------------------------------------------------------
// Quantize / losses / indices — emb rows staged in smem (coalesced gather)
// ---------------------------------------------------------------------------
__global__ __launch_bounds__(256)
void quantize_kernel(const float* __restrict__ z, const float* __restrict__ emb,
                     float* __restrict__ out) {
    extern __shared__ float4 eq4[];     // [64][65] float4 = 66560 B
    float* eqf = (float*)eq4;
    __shared__ int bidx_s[64];
    __shared__ float red[256];
    const int tid = threadIdx.x;
    const int n0 = blockIdx.x * 64;
    const int bimg = n0 >> 10, hw0 = n0 & 1023;
    const float* zb = z + (size_t)bimg * CDIM * 1024 + hw0;
    const size_t QELEMS = (size_t)NROWS * CDIM;

    if (tid < 64) {
        int k = g_idx[n0 + tid];
        bidx_s[tid] = k;
        out[QELEMS + 2 + n0 + tid] = (float)k;
    }
    __syncthreads();

    const float4* emb4 = (const float4*)emb;
    #pragma unroll
    for (int i = 0; i < 16; i++) {
        int u = i * 256 + tid;
        int r = u >> 6, q = u & 63;
        eq4[r * 65 + q] = emb4[(size_t)bidx_s[r] * 64 + q];
    }
    __syncthreads();

    float lsum = 0.f;
    for (int e = tid; e < 64 * CDIM; e += 256) {
        int c = e >> 6, m = e & 63;
        float qv = eqf[m * 260 + c];
        float zv = zb[(size_t)c * 1024 + m];
        float d  = __fsub_rn(qv, zv);
        out[(size_t)bimg * CDIM * 1024 + (size_t)c * 1024 + hw0 + m] = __fadd_rn(zv, d);
        lsum = __fmaf_rn(d, d, lsum);
    }
    red[tid] = lsum;
    __syncthreads();
    #pragma unroll
    for (int st = 128; st; st >>= 1) {
        if (tid < st) red[tid] += red[tid + st];
        __syncthreads();
    }
    if (tid == 0) g_partial[blockIdx.x] = red[0];
}

__global__ void finalize_kernel(float* __restrict__ out) {
    __shared__ float red[256];
    red[threadIdx.x] = g_partial[threadIdx.x];
    __syncthreads();
    #pragma unroll
    for (int st = 128; st; st >>= 1) {
        if (threadIdx.x < st) red[threadIdx.x] += red[threadIdx.x + st];
        __syncthreads();
    }
    if (threadIdx.x == 0) {
        const size_t QELEMS = (size_t)NROWS * CDIM;
        float loss = red[0] / (float)QELEMS;
        out[QELEMS]     = loss;
        out[QELEMS + 1] = 0.25f * loss;
    }
}

// ---------------------------------------------------------------------------
extern "C" void kernel_launch(void* const* d_in, const int* in_sizes, int n_in,
                              void* d_out, int out_size) {
    const float* z   = (const float*)d_in[0];
    const float* emb = (const float*)d_in[1];
    float* out = (float*)d_out;

    constexpr int PREP_SMEM = 66560;
    constexpr int RESC_SMEM = 66560 + 2048;
    cudaFuncSetAttribute(gemm_screen_kernel,
                         cudaFuncAttributeMaxDynamicSharedMemorySize, SM_TOTAL);
    cudaFuncSetAttribute(conv_az_kernel,
                         cudaFuncAttributeMaxDynamicSharedMemorySize, PREP_SMEM);
    cudaFuncSetAttribute(conv_bc_kernel,
                         cudaFuncAttributeMaxDynamicSharedMemorySize, PREP_SMEM);
    cudaFuncSetAttribute(rescore_kernel,
                         cudaFuncAttributeMaxDynamicSharedMemorySize, RESC_SMEM);
    cudaFuncSetAttribute(quantize_kernel,
                         cudaFuncAttributeMaxDynamicSharedMemorySize, PREP_SMEM);

    conv_az_kernel<<<NROWS / 64, 256, PREP_SMEM>>>(z);
    conv_bc_kernel<<<KCODES / 64, 256, PREP_SMEM>>>(emb);
    gemm_screen_kernel<<<NROWS / MT, GTHREADS, SM_TOTAL>>>();
    rescore_kernel<<<NROWS / 64, 256, RESC_SMEM>>>(z, emb);
    quantize_kernel<<<NROWS / 64, 256, PREP_SMEM>>>(z, emb, out);
    finalize_kernel<<<1, 256>>>(out);
}

// round 14
// speedup vs baseline: 401.3438x; 1.0931x over previous
#include <cuda_runtime.h>
#include <cuda_bf16.h>
#include <cstdint>
#include <math_constants.h>

#define CDIM 256
#define KCODES 8192
#define NROWS 16384
#define NT 128              // codes per chunk
#define MT 128              // rows per CTA
#define NCHUNKS (KCODES / NT)
#define CAP 128             // candidate slots per row
#define MARGIN 1.0e-3f      // insertion margin (time-varying runmax safety)
#define RWIN   4.0e-4f      // rescore window (hard bf16-error bound + slack)
#define GTHREADS 512

// ---------------------------------------------------------------------------
// Device globals (allocation-free scratch)
// ---------------------------------------------------------------------------
__device__ __align__(16) __nv_bfloat16 g_Abf[(size_t)NROWS * CDIM];   // [n][c]
__device__ __align__(16) __nv_bfloat16 g_Bbf[(size_t)KCODES * CDIM];  // [k][c]
__device__ float    g_A[NROWS];                          // exact ||x||^2 (strict seq)
__device__ float    g_C[KCODES];                         // exact ||e||^2 (strict seq)
__device__ unsigned g_candk[(size_t)NROWS * CAP];
__device__ float    g_cands[(size_t)NROWS * CAP];
__device__ int      g_cnt[NROWS];
__device__ float    g_thresh[NROWS];
__device__ int      g_idx[NROWS];
__device__ float    g_partial[NROWS / 64];

// ---------------------------------------------------------------------------
// Helpers
// ---------------------------------------------------------------------------
__device__ __forceinline__ uint32_t smem_to_u32(const void* p) {
    uint32_t a;
    asm("{ .reg .u64 t; cvta.to.shared.u64 t, %1; cvt.u32.u64 %0, t; }" : "=r"(a) : "l"(p));
    return a;
}
__device__ __forceinline__ unsigned f2ord(float f) {
    unsigned u = __float_as_uint(f);
    return (u & 0x80000000u) ? ~u : (u | 0x80000000u);
}
__device__ __forceinline__ float ord2f(unsigned u) {
    return __uint_as_float((u & 0x80000000u) ? (u ^ 0x80000000u) : ~u);
}
__device__ __forceinline__ void ldsm4(uint32_t r[4], uint32_t addr) {
    asm volatile("ldmatrix.sync.aligned.m8n8.x4.shared.b16 {%0,%1,%2,%3}, [%4];"
                 : "=r"(r[0]), "=r"(r[1]), "=r"(r[2]), "=r"(r[3]) : "r"(addr));
}
__device__ __forceinline__ void mma16816(float d[4], const uint32_t a[4],
                                         uint32_t b0, uint32_t b1) {
    asm("mma.sync.aligned.m16n8k16.row.col.f32.bf16.bf16.f32 "
        "{%0,%1,%2,%3}, {%4,%5,%6,%7}, {%8,%9}, {%0,%1,%2,%3};"
        : "+f"(d[0]), "+f"(d[1]), "+f"(d[2]), "+f"(d[3])
        : "r"(a[0]), "r"(a[1]), "r"(a[2]), "r"(a[3]), "r"(b0), "r"(b1));
}
__device__ __forceinline__ void cp16(uint32_t dst, const void* src) {
    asm volatile("cp.async.cg.shared.global [%0], [%1], 16;" :: "r"(dst), "l"(src) : "memory");
}
#define CP_COMMIT() asm volatile("cp.async.commit_group;" ::: "memory")
#define CP_WAIT0()  asm volatile("cp.async.wait_group 0;" ::: "memory")
#define BAR_NAMED(id, cnt) asm volatile("bar.sync %0, %1;" :: "r"(id), "r"(cnt) : "memory")

// ---------------------------------------------------------------------------
// Fused prep: z -> bf16 transposed tile + exact row norms A (strict seq).
// ---------------------------------------------------------------------------
__global__ __launch_bounds__(256)
void conv_az_kernel(const float* __restrict__ z) {
    extern __shared__ float tile[];     // [256][65] floats = 66560 B
    const int tid = threadIdx.x;
    const int n0 = blockIdx.x * 64;
    const int b = n0 >> 10, hw0 = n0 & 1023;
    const int m = tid & 63, c_lo = tid >> 6;

    #pragma unroll 4
    for (int i = 0; i < 64; i++) {
        int c = i * 4 + c_lo;
        tile[c * 65 + m] = z[((size_t)b * CDIM + c) * 1024 + hw0 + m];
    }
    __syncthreads();

    __nv_bfloat162* dst = (__nv_bfloat162*)g_Abf;
    #pragma unroll
    for (int i = 0; i < 32; i++) {
        int u = i * 256 + tid;
        int mm = u >> 7, c2 = u & 127;
        dst[(size_t)(n0 + mm) * 128 + c2] =
            __floats2bfloat162_rn(tile[(2 * c2) * 65 + mm], tile[(2 * c2 + 1) * 65 + mm]);
    }

    if (tid < 64) {
        float s = 0.f;
        #pragma unroll 16
        for (int c = 0; c < CDIM; c++) {
            float v = tile[c * 65 + tid];
            s = __fadd_rn(s, __fmul_rn(v, v));
        }
        g_A[n0 + tid] = s;
    }
}

// ---------------------------------------------------------------------------
// Fused prep: emb -> bf16 + exact code norms C (strict seq).
// ---------------------------------------------------------------------------
__global__ __launch_bounds__(256)
void conv_bc_kernel(const float* __restrict__ emb) {
    extern __shared__ float4 esm[];     // [64][65] float4 = 66560 B
    float* esf = (float*)esm;
    const int tid = threadIdx.x;
    const int k0 = blockIdx.x * 64;
    const float4* src = (const float4*)(emb + (size_t)k0 * CDIM);

    #pragma unroll
    for (int i = 0; i < 16; i++) {
        int g = i * 256 + tid;
        int r = g >> 6, q = g & 63;
        esm[r * 65 + q] = src[g];
    }
    __syncthreads();

    __nv_bfloat162* dst = (__nv_bfloat162*)g_Bbf;
    #pragma unroll
    for (int i = 0; i < 32; i++) {
        int u = i * 256 + tid;
        int r = u >> 7, c2 = u & 127;
        dst[(size_t)(k0 + r) * 128 + c2] =
            __floats2bfloat162_rn(esf[r * 260 + 2 * c2], esf[r * 260 + 2 * c2 + 1]);
    }

    if (tid < 64) {
        float s = 0.f;
        #pragma unroll 8
        for (int q = 0; q < 64; q++) {
            float4 v = esm[tid * 65 + q];
            s = __fadd_rn(s, __fmul_rn(v.x, v.x));
            s = __fadd_rn(s, __fmul_rn(v.y, v.y));
            s = __fadd_rn(s, __fmul_rn(v.z, v.z));
            s = __fadd_rn(s, __fmul_rn(v.w, v.w));
        }
        g_C[k0 + tid] = s;
    }
}

// ---------------------------------------------------------------------------
// GEMM (HMMA mma.sync bf16 f32-acc) + two-pass screening (R7/R11-validated)
// ---------------------------------------------------------------------------
#define SM_A 0
#define SM_B0 65536
#define SM_B1 131072
#define SM_C  196608
#define SM_RMAX (SM_C + 1024)
#define SM_CNT  (SM_RMAX + 512)
#define SM_TOTAL (SM_CNT + 512)

__device__ __forceinline__ void cp_tile(uint32_t dst, const __nv_bfloat16* gsrc, int tid) {
    const char* src = (const char*)gsrc;
    #pragma unroll
    for (int it = 0; it < 8; it++) {
        int u = it * GTHREADS + tid;
        int row = u >> 5, gr = u & 31;
        cp16(dst + row * 512 + ((gr ^ (row & 7)) << 4), src + (size_t)u * 16);
    }
}

__global__ __launch_bounds__(GTHREADS, 1)
void gemm_screen_kernel() {
    extern __shared__ char smem[];
    const uint32_t smem_base = smem_to_u32(smem);
    const int tid = threadIdx.x;
    const int wid = tid >> 5, lane = tid & 31;
    const int wm = wid & 3, wn = wid >> 2;
    const int g = lane >> 2, tg = lane & 3;
    const int n0 = blockIdx.x * MT;

    float*    C_s     = (float*)(smem + SM_C);
    unsigned* sh_rmax = (unsigned*)(smem + SM_RMAX);
    int*      sh_cnt  = (int*)(smem + SM_CNT);

    if (tid < 128) { sh_rmax[tid] = f2ord(-CUDART_INF_F); sh_cnt[tid] = 0; }

    cp_tile(smem_base + SM_A, g_Abf + (size_t)n0 * CDIM, tid);
    cp_tile(smem_base + SM_B0, g_Bbf, tid);
    CP_COMMIT();
    if (tid < 128) C_s[tid] = g_C[tid];
    CP_WAIT0();
    __syncthreads();

    const uint32_t As_base = smem_base + SM_A;

    for (int i = 0; i < NCHUNKS; i++) {
        const int cur = i & 1, nxt = cur ^ 1;

        if (i + 1 < NCHUNKS) {
            cp_tile(smem_base + (nxt ? SM_B1 : SM_B0),
                    g_Bbf + (size_t)(i + 1) * NT * CDIM, tid);
            CP_COMMIT();
            if (tid < 128) C_s[nxt * 128 + tid] = g_C[(i + 1) * NT + tid];
        }

        const uint32_t Bs_base = smem_base + (cur ? SM_B1 : SM_B0);
        float acc[2][4][4];
        #pragma unroll
        for (int mt = 0; mt < 2; mt++)
            #pragma unroll
            for (int nt = 0; nt < 4; nt++)
                #pragma unroll
                for (int c = 0; c < 4; c++) acc[mt][nt][c] = 0.f;

        #pragma unroll
        for (int ks = 0; ks < 16; ks++) {
            uint32_t a_frag[2][4];
            #pragma unroll
            for (int mt = 0; mt < 2; mt++) {
                int row = wm * 32 + mt * 16 + (lane & 15);
                int gr  = ks * 2 + (lane >> 4);
                ldsm4(a_frag[mt], As_base + row * 512 + ((gr ^ (row & 7)) << 4));
            }
            uint32_t b_frag[2][4];
            #pragma unroll
            for (int bp = 0; bp < 2; bp++) {
                int n  = wn * 32 + bp * 16 + ((lane >> 4) << 3) + (lane & 7);
                int gr = ks * 2 + ((lane >> 3) & 1);
                ldsm4(b_frag[bp], Bs_base + n * 512 + ((gr ^ (n & 7)) << 4));
            }
            #pragma unroll
            for (int mt = 0; mt < 2; mt++)
                #pragma unroll
                for (int bp = 0; bp < 2; bp++) {
                    mma16816(acc[mt][bp * 2],     a_frag[mt], b_frag[bp][0], b_frag[bp][1]);
                    mma16816(acc[mt][bp * 2 + 1], a_frag[mt], b_frag[bp][2], b_frag[bp][3]);
                }
        }

        // PASS 1: scores in-place + chunk row-max
        #pragma unroll
        for (int mt = 0; mt < 2; mt++) {
            float lmax[2] = {-CUDART_INF_F, -CUDART_INF_F};
            #pragma unroll
            for (int nt = 0; nt < 4; nt++)
                #pragma unroll
                for (int h = 0; h < 2; h++)
                    #pragma unroll
                    for (int q = 0; q < 2; q++) {
                        int col = wn * 32 + nt * 8 + tg * 2 + q;
                        float s = __fmaf_rn(2.0f, acc[mt][nt][h * 2 + q],
                                            -C_s[cur * 128 + col]);
                        acc[mt][nt][h * 2 + q] = s;
                        if (s > lmax[h]) lmax[h] = s;
                    }
            #pragma unroll
            for (int h = 0; h < 2; h++) {
                lmax[h] = fmaxf(lmax[h], __shfl_xor_sync(0xffffffffu, lmax[h], 1));
                lmax[h] = fmaxf(lmax[h], __shfl_xor_sync(0xffffffffu, lmax[h], 2));
                if (tg == 0) {
                    int rl = wm * 32 + mt * 16 + h * 8 + g;
                    atomicMax(&sh_rmax[rl], f2ord(lmax[h]));
                }
            }
        }
        BAR_NAMED(1 + wm, 128);   // only the 4 wn-warps sharing rows must agree

        // PASS 2: insert candidates above updated threshold
        const int k0 = i * NT;
        #pragma unroll
        for (int mt = 0; mt < 2; mt++)
            #pragma unroll
            for (int h = 0; h < 2; h++) {
                int rl = wm * 32 + mt * 16 + h * 8 + g;
                float thr = ord2f(sh_rmax[rl]) - MARGIN;
                #pragma unroll
                for (int nt = 0; nt < 4; nt++)
                    #pragma unroll
                    for (int q = 0; q < 2; q++) {
                        float s = acc[mt][nt][h * 2 + q];
                        if (s > thr) {
                            int col = wn * 32 + nt * 8 + tg * 2 + q;
                            int slot = atomicAdd(&sh_cnt[rl], 1);
                            if (slot < CAP) {
                                g_candk[(size_t)(n0 + rl) * CAP + slot] = (unsigned)(k0 + col);
                                g_cands[(size_t)(n0 + rl) * CAP + slot] = s;
                            }
                        }
                    }
            }
        if (i + 1 < NCHUNKS) CP_WAIT0();
        __syncthreads();
    }

    if (tid < 128) {
        g_cnt[n0 + tid] = sh_cnt[tid];
        g_thresh[n0 + tid] = ord2f(sh_rmax[tid]) - MARGIN;
    }
}

// ---------------------------------------------------------------------------
// Rescore v4: 32 rows/block, 8 threads/row, z tile in smem, tight RWIN filter.
// Only candidates with s >= runmax - RWIN can be the reference argmin
// (hard bf16-error bound 2^-8*||x||*||e|| + fp32/reference-ULP slack < RWIN);
// all such candidates are guaranteed stored (RWIN < MARGIN at all times).
// Exact fp32 chain ascending c (bit-exact, R2-validated order).
// ---------------------------------------------------------------------------
__device__ __forceinline__ float exact_d_s(const float* __restrict__ zrow,
                                           const float4* __restrict__ e4,
                                           float A, float C) {
    float P = 0.f;
    #pragma unroll
    for (int c0 = 0; c0 < CDIM; c0 += 16) {
        float4 ev[4];
        #pragma unroll
        for (int u = 0; u < 4; u++) ev[u] = __ldg(e4 + (c0 >> 2) + u);
        #pragma unroll
        for (int u = 0; u < 4; u++) {
            P = __fmaf_rn(zrow[(c0 + 4 * u + 0) * 33], ev[u].x, P);
            P = __fmaf_rn(zrow[(c0 + 4 * u + 1) * 33], ev[u].y, P);
            P = __fmaf_rn(zrow[(c0 + 4 * u + 2) * 33], ev[u].z, P);
            P = __fmaf_rn(zrow[(c0 + 4 * u + 3) * 33], ev[u].w, P);
        }
    }
    float t = __fsub_rn(A, __fmul_rn(2.0f, P));
    return __fadd_rn(t, C);
}

__global__ __launch_bounds__(256)
void rescore_kernel(const float* __restrict__ z, const float* __restrict__ emb) {
    extern __shared__ float rsm[];           // tile [256][33] + bd[256] + bi[256]
    float* tile = rsm;                        // 33792 B
    float* s_bd = rsm + 256 * 33;             // 1024 B
    int*   s_bi = (int*)(s_bd + 256);         // 1024 B

    const int tid = threadIdx.x;
    const int n0 = blockIdx.x * 32;
    const int b = n0 >> 10, hw0 = n0 & 1023;

    // Stage z tile [c][m], coalesced over m (warp = one 128B row-slice)
    {
        const int m = tid & 31, c_lo = tid >> 5;
        #pragma unroll 4
        for (int i = 0; i < 32; i++) {
            int c = i * 8 + c_lo;
            tile[c * 33 + m] = z[((size_t)b * CDIM + c) * 1024 + hw0 + m];
        }
    }
    __syncthreads();

    const int m = tid & 31;                  // row within block
    const int part = tid >> 5;               // 0..7 candidate partition
    const int n = n0 + m;
    const float A = g_A[n];
    const int cnt = g_cnt[n];
    const float rcut = (g_thresh[n] + MARGIN) - RWIN;   // runmax - RWIN
    const float* zrow = tile + m;

    float bd = CUDART_INF_F;
    int bi = 0x7fffffff;

    if (cnt <= CAP) {
        for (int l = part; l < cnt; l += 8) {
            float s = g_cands[(size_t)n * CAP + l];
            if (s >= rcut) {
                int k = (int)g_candk[(size_t)n * CAP + l];
                float d = exact_d_s(zrow, (const float4*)(emb + (size_t)k * CDIM),
                                    A, g_C[k]);
                if (d < bd || (d == bd && k < bi)) { bd = d; bi = k; }
            }
        }
    } else {  // overflow fallback (never fires; safety): split full scan 8-way
        for (int k = part; k < KCODES; k += 8) {
            float d = exact_d_s(zrow, (const float4*)(emb + (size_t)k * CDIM),
                                A, g_C[k]);
            if (d < bd || (d == bd && k < bi)) { bd = d; bi = k; }
        }
    }
    s_bd[tid] = bd;
    s_bi[tid] = bi;
    __syncthreads();

    // Merge the 8 partitions in fixed order (deterministic total order on (d,k))
    if (tid < 32) {
        float fbd = s_bd[tid];
        int   fbi = s_bi[tid];
        #pragma unroll
        for (int j = 1; j < 8; j++) {
            float od = s_bd[tid + j * 32];
            int   oi = s_bi[tid + j * 32];
            if (od < fbd || (od == fbd && oi < fbi)) { fbd = od; fbi = oi; }
        }
        g_idx[n0 + tid] = fbi;
    }
}

// ---------------------------------------------------------------------------
// Quantize / losses / indices — emb rows staged in smem (coalesced gather)
// ---------------------------------------------------------------------------
__global__ __launch_bounds__(256)
void quantize_kernel(const float* __restrict__ z, const float* __restrict__ emb,
                     float* __restrict__ out) {
    extern __shared__ float4 eq4[];     // [64][65] float4 = 66560 B
    float* eqf = (float*)eq4;
    __shared__ int bidx_s[64];
    __shared__ float red[256];
    const int tid = threadIdx.x;
    const int n0 = blockIdx.x * 64;
    const int bimg = n0 >> 10, hw0 = n0 & 1023;
    const float* zb = z + (size_t)bimg * CDIM * 1024 + hw0;
    const size_t QELEMS = (size_t)NROWS * CDIM;

    if (tid < 64) {
        int k = g_idx[n0 + tid];
        bidx_s[tid] = k;
        out[QELEMS + 2 + n0 + tid] = (float)k;
    }
    __syncthreads();

    const float4* emb4 = (const float4*)emb;
    #pragma unroll
    for (int i = 0; i < 16; i++) {
        int u = i * 256 + tid;
        int r = u >> 6, q = u & 63;
        eq4[r * 65 + q] = emb4[(size_t)bidx_s[r] * 64 + q];
    }
    __syncthreads();

    float lsum = 0.f;
    for (int e = tid; e < 64 * CDIM; e += 256) {
        int c = e >> 6, m = e & 63;
        float qv = eqf[m * 260 + c];
        float zv = zb[(size_t)c * 1024 + m];
        float d  = __fsub_rn(qv, zv);
        out[(size_t)bimg * CDIM * 1024 + (size_t)c * 1024 + hw0 + m] = __fadd_rn(zv, d);
        lsum = __fmaf_rn(d, d, lsum);
    }
    red[tid] = lsum;
    __syncthreads();
    #pragma unroll
    for (int st = 128; st; st >>= 1) {
        if (tid < st) red[tid] += red[tid + st];
        __syncthreads();
    }
    if (tid == 0) g_partial[blockIdx.x] = red[0];
}

__global__ void finalize_kernel(float* __restrict__ out) {
    __shared__ float red[256];
    red[threadIdx.x] = g_partial[threadIdx.x];
    __syncthreads();
    #pragma unroll
    for (int st = 128; st; st >>= 1) {
        if (threadIdx.x < st) red[threadIdx.x] += red[threadIdx.x + st];
        __syncthreads();
    }
    if (threadIdx.x == 0) {
        const size_t QELEMS = (size_t)NROWS * CDIM;
        float loss = red[0] / (float)QELEMS;
        out[QELEMS]     = loss;
        out[QELEMS + 1] = 0.25f * loss;
    }
}

// ---------------------------------------------------------------------------
extern "C" void kernel_launch(void* const* d_in, const int* in_sizes, int n_in,
                              void* d_out, int out_size) {
    const float* z   = (const float*)d_in[0];
    const float* emb = (const float*)d_in[1];
    float* out = (float*)d_out;

    constexpr int PREP_SMEM = 66560;
    constexpr int RESC_SMEM = 256 * 33 * 4 + 2048;   // 35840
    cudaFuncSetAttribute(gemm_screen_kernel,
                         cudaFuncAttributeMaxDynamicSharedMemorySize, SM_TOTAL);
    cudaFuncSetAttribute(conv_az_kernel,
                         cudaFuncAttributeMaxDynamicSharedMemorySize, PREP_SMEM);
    cudaFuncSetAttribute(conv_bc_kernel,
                         cudaFuncAttributeMaxDynamicSharedMemorySize, PREP_SMEM);
    cudaFuncSetAttribute(rescore_kernel,
                         cudaFuncAttributeMaxDynamicSharedMemorySize, RESC_SMEM);
    cudaFuncSetAttribute(quantize_kernel,
                         cudaFuncAttributeMaxDynamicSharedMemorySize, PREP_SMEM);

    conv_az_kernel<<<NROWS / 64, 256, PREP_SMEM>>>(z);
    conv_bc_kernel<<<KCODES / 64, 256, PREP_SMEM>>>(emb);
    gemm_screen_kernel<<<NROWS / MT, GTHREADS, SM_TOTAL>>>();
    rescore_kernel<<<NROWS / 32, 256, RESC_SMEM>>>(z, emb);
    quantize_kernel<<<NROWS / 64, 256, PREP_SMEM>>>(z, emb, out);
    finalize_kernel<<<1, 256>>>(out);
}

// round 15
// speedup vs baseline: 457.2712x; 1.1394x over previous
#include <cuda_runtime.h>
#include <cuda_bf16.h>
#include <cstdint>
#include <math_constants.h>

#define CDIM 256
#define KCODES 8192
#define NROWS 16384
#define NT 128              // codes per chunk
#define MT 128              // rows per CTA
#define NCHUNKS (KCODES / NT)
#define CAP 256             // candidate slots per row (single-pass headroom)
#define MARGIN 1.0e-3f      // insertion margin
#define RWIN   4.0e-4f      // rescore window (hard bf16-error bound + slack)
#define GTHREADS 512
#define CLIST 32            // per-row compacted window-set capacity

// ---------------------------------------------------------------------------
// Device globals (allocation-free scratch)
// ---------------------------------------------------------------------------
__device__ __align__(16) __nv_bfloat16 g_Abf[(size_t)NROWS * CDIM];   // [n][c]
__device__ __align__(16) __nv_bfloat16 g_Bbf[(size_t)KCODES * CDIM];  // [k][c]
__device__ float    g_A[NROWS];                          // exact ||x||^2 (strict seq)
__device__ float    g_C[KCODES];                         // exact ||e||^2 (strict seq)
__device__ unsigned g_candk[(size_t)NROWS * CAP];
__device__ float    g_cands[(size_t)NROWS * CAP];
__device__ int      g_cnt[NROWS];
__device__ float    g_thresh[NROWS];
__device__ float    g_partial[NROWS / 32];

// ---------------------------------------------------------------------------
// Helpers
// ---------------------------------------------------------------------------
__device__ __forceinline__ uint32_t smem_to_u32(const void* p) {
    uint32_t a;
    asm("{ .reg .u64 t; cvta.to.shared.u64 t, %1; cvt.u32.u64 %0, t; }" : "=r"(a) : "l"(p));
    return a;
}
__device__ __forceinline__ unsigned f2ord(float f) {
    unsigned u = __float_as_uint(f);
    return (u & 0x80000000u) ? ~u : (u | 0x80000000u);
}
__device__ __forceinline__ float ord2f(unsigned u) {
    return __uint_as_float((u & 0x80000000u) ? (u ^ 0x80000000u) : ~u);
}
__device__ __forceinline__ void ldsm4(uint32_t r[4], uint32_t addr) {
    asm volatile("ldmatrix.sync.aligned.m8n8.x4.shared.b16 {%0,%1,%2,%3}, [%4];"
                 : "=r"(r[0]), "=r"(r[1]), "=r"(r[2]), "=r"(r[3]) : "r"(addr));
}
__device__ __forceinline__ void mma16816(float d[4], const uint32_t a[4],
                                         uint32_t b0, uint32_t b1) {
    asm("mma.sync.aligned.m16n8k16.row.col.f32.bf16.bf16.f32 "
        "{%0,%1,%2,%3}, {%4,%5,%6,%7}, {%8,%9}, {%0,%1,%2,%3};"
        : "+f"(d[0]), "+f"(d[1]), "+f"(d[2]), "+f"(d[3])
        : "r"(a[0]), "r"(a[1]), "r"(a[2]), "r"(a[3]), "r"(b0), "r"(b1));
}
__device__ __forceinline__ void cp16(uint32_t dst, const void* src) {
    asm volatile("cp.async.cg.shared.global [%0], [%1], 16;" :: "r"(dst), "l"(src) : "memory");
}
#define CP_COMMIT() asm volatile("cp.async.commit_group;" ::: "memory")
#define CP_WAIT0()  asm volatile("cp.async.wait_group 0;" ::: "memory")
#define BAR_NAMED(id, cnt) asm volatile("bar.sync %0, %1;" :: "r"(id), "r"(cnt) : "memory")

// ---------------------------------------------------------------------------
// Fused prep: z -> bf16 transposed tile + exact row norms A (strict seq).
// ---------------------------------------------------------------------------
__global__ __launch_bounds__(256)
void conv_az_kernel(const float* __restrict__ z) {
    extern __shared__ float tile[];     // [256][65] floats = 66560 B
    const int tid = threadIdx.x;
    const int n0 = blockIdx.x * 64;
    const int b = n0 >> 10, hw0 = n0 & 1023;
    const int m = tid & 63, c_lo = tid >> 6;

    #pragma unroll 4
    for (int i = 0; i < 64; i++) {
        int c = i * 4 + c_lo;
        tile[c * 65 + m] = z[((size_t)b * CDIM + c) * 1024 + hw0 + m];
    }
    __syncthreads();

    __nv_bfloat162* dst = (__nv_bfloat162*)g_Abf;
    #pragma unroll
    for (int i = 0; i < 32; i++) {
        int u = i * 256 + tid;
        int mm = u >> 7, c2 = u & 127;
        dst[(size_t)(n0 + mm) * 128 + c2] =
            __floats2bfloat162_rn(tile[(2 * c2) * 65 + mm], tile[(2 * c2 + 1) * 65 + mm]);
    }

    if (tid < 64) {
        float s = 0.f;
        #pragma unroll 16
        for (int c = 0; c < CDIM; c++) {
            float v = tile[c * 65 + tid];
            s = __fadd_rn(s, __fmul_rn(v, v));
        }
        g_A[n0 + tid] = s;
    }
}

// ---------------------------------------------------------------------------
// Fused prep: emb -> bf16 + exact code norms C (strict seq).
// ---------------------------------------------------------------------------
__global__ __launch_bounds__(256)
void conv_bc_kernel(const float* __restrict__ emb) {
    extern __shared__ float4 esm[];     // [64][65] float4 = 66560 B
    float* esf = (float*)esm;
    const int tid = threadIdx.x;
    const int k0 = blockIdx.x * 64;
    const float4* src = (const float4*)(emb + (size_t)k0 * CDIM);

    #pragma unroll
    for (int i = 0; i < 16; i++) {
        int g = i * 256 + tid;
        int r = g >> 6, q = g & 63;
        esm[r * 65 + q] = src[g];
    }
    __syncthreads();

    __nv_bfloat162* dst = (__nv_bfloat162*)g_Bbf;
    #pragma unroll
    for (int i = 0; i < 32; i++) {
        int u = i * 256 + tid;
        int r = u >> 7, c2 = u & 127;
        dst[(size_t)(k0 + r) * 128 + c2] =
            __floats2bfloat162_rn(esf[r * 260 + 2 * c2], esf[r * 260 + 2 * c2 + 1]);
    }

    if (tid < 64) {
        float s = 0.f;
        #pragma unroll 8
        for (int q = 0; q < 64; q++) {
            float4 v = esm[tid * 65 + q];
            s = __fadd_rn(s, __fmul_rn(v.x, v.x));
            s = __fadd_rn(s, __fmul_rn(v.y, v.y));
            s = __fadd_rn(s, __fmul_rn(v.z, v.z));
            s = __fadd_rn(s, __fmul_rn(v.w, v.w));
        }
        g_C[k0 + tid] = s;
    }
}

// ---------------------------------------------------------------------------
// GEMM (HMMA mma.sync bf16 f32-acc) + screening.
// Chunk 0: two-pass (seeds runmax). Chunks >= 1: single pass against the
// pre-chunk threshold (register-cached) — thr only grows, so every code
// within MARGIN of the FINAL max is still captured.
// ---------------------------------------------------------------------------
#define SM_A 0
#define SM_B0 65536
#define SM_B1 131072
#define SM_C  196608
#define SM_RMAX (SM_C + 1024)
#define SM_CNT  (SM_RMAX + 512)
#define SM_TOTAL (SM_CNT + 512)

__device__ __forceinline__ void cp_tile(uint32_t dst, const __nv_bfloat16* gsrc, int tid) {
    const char* src = (const char*)gsrc;
    #pragma unroll
    for (int it = 0; it < 8; it++) {
        int u = it * GTHREADS + tid;
        int row = u >> 5, gr = u & 31;
        cp16(dst + row * 512 + ((gr ^ (row & 7)) << 4), src + (size_t)u * 16);
    }
}

__global__ __launch_bounds__(GTHREADS, 1)
void gemm_screen_kernel() {
    extern __shared__ char smem[];
    const uint32_t smem_base = smem_to_u32(smem);
    const int tid = threadIdx.x;
    const int wid = tid >> 5, lane = tid & 31;
    const int wm = wid & 3, wn = wid >> 2;
    const int g = lane >> 2, tg = lane & 3;
    const int n0 = blockIdx.x * MT;

    float*    C_s     = (float*)(smem + SM_C);
    unsigned* sh_rmax = (unsigned*)(smem + SM_RMAX);
    int*      sh_cnt  = (int*)(smem + SM_CNT);

    if (tid < 128) { sh_rmax[tid] = f2ord(-CUDART_INF_F); sh_cnt[tid] = 0; }

    cp_tile(smem_base + SM_A, g_Abf + (size_t)n0 * CDIM, tid);
    cp_tile(smem_base + SM_B0, g_Bbf, tid);
    CP_COMMIT();
    if (tid < 128) C_s[tid] = g_C[tid];
    CP_WAIT0();
    __syncthreads();

    const uint32_t As_base = smem_base + SM_A;

    for (int i = 0; i < NCHUNKS; i++) {
        const int cur = i & 1, nxt = cur ^ 1;

        if (i + 1 < NCHUNKS) {
            cp_tile(smem_base + (nxt ? SM_B1 : SM_B0),
                    g_Bbf + (size_t)(i + 1) * NT * CDIM, tid);
            CP_COMMIT();
            if (tid < 128) C_s[nxt * 128 + tid] = g_C[(i + 1) * NT + tid];
        }

        // Pre-chunk thresholds (valid for i >= 1: sh_rmax covers chunks < i)
        float thr[2][2];
        #pragma unroll
        for (int mt = 0; mt < 2; mt++)
            #pragma unroll
            for (int h = 0; h < 2; h++)
                thr[mt][h] = ord2f(sh_rmax[wm * 32 + mt * 16 + h * 8 + g]) - MARGIN;

        // ---- compute chunk i ----
        const uint32_t Bs_base = smem_base + (cur ? SM_B1 : SM_B0);
        float acc[2][4][4];
        #pragma unroll
        for (int mt = 0; mt < 2; mt++)
            #pragma unroll
            for (int nt = 0; nt < 4; nt++)
                #pragma unroll
                for (int c = 0; c < 4; c++) acc[mt][nt][c] = 0.f;

        #pragma unroll
        for (int ks = 0; ks < 16; ks++) {
            uint32_t a_frag[2][4];
            #pragma unroll
            for (int mt = 0; mt < 2; mt++) {
                int row = wm * 32 + mt * 16 + (lane & 15);
                int gr  = ks * 2 + (lane >> 4);
                ldsm4(a_frag[mt], As_base + row * 512 + ((gr ^ (row & 7)) << 4));
            }
            uint32_t b_frag[2][4];
            #pragma unroll
            for (int bp = 0; bp < 2; bp++) {
                int n  = wn * 32 + bp * 16 + ((lane >> 4) << 3) + (lane & 7);
                int gr = ks * 2 + ((lane >> 3) & 1);
                ldsm4(b_frag[bp], Bs_base + n * 512 + ((gr ^ (n & 7)) << 4));
            }
            #pragma unroll
            for (int mt = 0; mt < 2; mt++)
                #pragma unroll
                for (int bp = 0; bp < 2; bp++) {
                    mma16816(acc[mt][bp * 2],     a_frag[mt], b_frag[bp][0], b_frag[bp][1]);
                    mma16816(acc[mt][bp * 2 + 1], a_frag[mt], b_frag[bp][2], b_frag[bp][3]);
                }
        }

        // scores in-place + chunk row-max -> sh_rmax
        #pragma unroll
        for (int mt = 0; mt < 2; mt++) {
            float lmax[2] = {-CUDART_INF_F, -CUDART_INF_F};
            #pragma unroll
            for (int nt = 0; nt < 4; nt++)
                #pragma unroll
                for (int h = 0; h < 2; h++)
                    #pragma unroll
                    for (int q = 0; q < 2; q++) {
                        int col = wn * 32 + nt * 8 + tg * 2 + q;
                        float s = __fmaf_rn(2.0f, acc[mt][nt][h * 2 + q],
                                            -C_s[cur * 128 + col]);
                        acc[mt][nt][h * 2 + q] = s;
                        if (s > lmax[h]) lmax[h] = s;
                    }
            #pragma unroll
            for (int h = 0; h < 2; h++) {
                lmax[h] = fmaxf(lmax[h], __shfl_xor_sync(0xffffffffu, lmax[h], 1));
                lmax[h] = fmaxf(lmax[h], __shfl_xor_sync(0xffffffffu, lmax[h], 2));
                if (tg == 0) {
                    int rl = wm * 32 + mt * 16 + h * 8 + g;
                    atomicMax(&sh_rmax[rl], f2ord(lmax[h]));
                }
            }
        }
        if (i == 0) {   // seed: wait for full chunk-0 max, then take fresh thr
            BAR_NAMED(1 + wm, 128);
            #pragma unroll
            for (int mt = 0; mt < 2; mt++)
                #pragma unroll
                for (int h = 0; h < 2; h++)
                    thr[mt][h] = ord2f(sh_rmax[wm * 32 + mt * 16 + h * 8 + g]) - MARGIN;
        }

        // insert candidates above threshold
        const int k0 = i * NT;
        #pragma unroll
        for (int mt = 0; mt < 2; mt++)
            #pragma unroll
            for (int h = 0; h < 2; h++) {
                int rl = wm * 32 + mt * 16 + h * 8 + g;
                #pragma unroll
                for (int nt = 0; nt < 4; nt++)
                    #pragma unroll
                    for (int q = 0; q < 2; q++) {
                        float s = acc[mt][nt][h * 2 + q];
                        if (s > thr[mt][h]) {
                            int col = wn * 32 + nt * 8 + tg * 2 + q;
                            int slot = atomicAdd(&sh_cnt[rl], 1);
                            if (slot < CAP) {
                                g_candk[(size_t)(n0 + rl) * CAP + slot] = (unsigned)(k0 + col);
                                g_cands[(size_t)(n0 + rl) * CAP + slot] = s;
                            }
                        }
                    }
            }
        if (i + 1 < NCHUNKS) CP_WAIT0();
        __syncthreads();
    }

    if (tid < 128) {
        g_cnt[n0 + tid] = sh_cnt[tid];
        g_thresh[n0 + tid] = ord2f(sh_rmax[tid]) - MARGIN;
    }
}

// ---------------------------------------------------------------------------
// Rescore v5 + fused quantize: 32 rows/block, 8 threads/row.
// Phase 1: compact window set (s >= runmax - RWIN) into smem per-row list.
//          |set|==1  ==> that code IS the argmin (RWIN >= hard error bound).
// Phase 2: exact fp32 chain evals (bit-exact order) on the compact list.
// Phase 3: quantized output + indices + loss partial (z tile reused).
// ---------------------------------------------------------------------------
__device__ __forceinline__ float exact_d_s(const float* __restrict__ zrow,
                                           const float4* __restrict__ e4,
                                           float A, float C) {
    float P = 0.f;
    #pragma unroll
    for (int c0 = 0; c0 < CDIM; c0 += 16) {
        float4 ev[4];
        #pragma unroll
        for (int u = 0; u < 4; u++) ev[u] = __ldg(e4 + (c0 >> 2) + u);
        #pragma unroll
        for (int u = 0; u < 4; u++) {
            P = __fmaf_rn(zrow[(c0 + 4 * u + 0) * 33], ev[u].x, P);
            P = __fmaf_rn(zrow[(c0 + 4 * u + 1) * 33], ev[u].y, P);
            P = __fmaf_rn(zrow[(c0 + 4 * u + 2) * 33], ev[u].z, P);
            P = __fmaf_rn(zrow[(c0 + 4 * u + 3) * 33], ev[u].w, P);
        }
    }
    float t = __fsub_rn(A, __fmul_rn(2.0f, P));
    return __fadd_rn(t, C);
}

__global__ __launch_bounds__(256)
void rescore_quant_kernel(const float* __restrict__ z, const float* __restrict__ emb,
                          float* __restrict__ out) {
    extern __shared__ float rsm[];
    float* tile  = rsm;                       // [256][33] = 33792 B
    float* s_bd  = rsm + 256 * 33;            // 256 f
    int*   s_bi  = (int*)(s_bd + 256);        // 256 i
    int*   s_cnt = s_bi + 256;                // 32 i
    int*   s_ck  = s_cnt + 32;                // 32*CLIST i
    int*   s_k   = s_ck + 32 * CLIST;         // 32 i

    const int tid = threadIdx.x;
    const int n0 = blockIdx.x * 32;
    const int b = n0 >> 10, hw0 = n0 & 1023;

    // Stage z tile [c][m], coalesced over m
    {
        const int mm = tid & 31, c_lo = tid >> 5;
        #pragma unroll 4
        for (int i = 0; i < 32; i++) {
            int c = i * 8 + c_lo;
            tile[c * 33 + mm] = z[((size_t)b * CDIM + c) * 1024 + hw0 + mm];
        }
    }
    if (tid < 32) s_cnt[tid] = 0;
    __syncthreads();

    const int m = tid & 31;                  // row within block
    const int part = tid >> 5;               // 0..7 partition
    const int n = n0 + m;
    const float A = g_A[n];
    const int cnt = g_cnt[n];
    const float rcut = (g_thresh[n] + MARGIN) - RWIN;   // runmax - RWIN
    const float* zrow = tile + m;

    // Phase 1: compact the window set
    const bool overflow = (cnt > CAP);
    if (!overflow) {
        for (int l = part; l < cnt; l += 8) {
            if (g_cands[(size_t)n * CAP + l] >= rcut) {
                int p = atomicAdd(&s_cnt[m], 1);
                if (p < CLIST) s_ck[m * CLIST + p] = (int)g_candk[(size_t)n * CAP + l];
            }
        }
    }
    __syncthreads();

    // Phase 2: exact evals on compact list
    const int rc = s_cnt[m];
    float bd = CUDART_INF_F;
    int bi = 0x7fffffff;
    if (overflow || rc == 0 || rc > CLIST) {
        for (int k = part; k < KCODES; k += 8) {   // safety net (never fires)
            float d = exact_d_s(zrow, (const float4*)(emb + (size_t)k * CDIM), A, g_C[k]);
            if (d < bd || (d == bd && k < bi)) { bd = d; bi = k; }
        }
    } else if (rc == 1) {
        if (part == 0) { bd = -CUDART_INF_F; bi = s_ck[m * CLIST]; }
    } else {
        for (int l = part; l < rc; l += 8) {
            int k = s_ck[m * CLIST + l];
            float d = exact_d_s(zrow, (const float4*)(emb + (size_t)k * CDIM), A, g_C[k]);
            if (d < bd || (d == bd && k < bi)) { bd = d; bi = k; }
        }
    }
    s_bd[tid] = bd;
    s_bi[tid] = bi;
    __syncthreads();

    // Merge partitions in fixed order (deterministic total order on (d,k))
    if (tid < 32) {
        float fbd = s_bd[tid];
        int   fbi = s_bi[tid];
        #pragma unroll
        for (int j = 1; j < 8; j++) {
            float od = s_bd[tid + j * 32];
            int   oi = s_bi[tid + j * 32];
            if (od < fbd || (od == fbd && oi < fbi)) { fbd = od; fbi = oi; }
        }
        s_k[tid] = fbi;
        out[(size_t)NROWS * CDIM + 2 + n0 + tid] = (float)fbi;
    }
    __syncthreads();

    // Phase 3: quantized_st + loss partial (z from smem tile)
    const float4* erow = (const float4*)emb + (size_t)s_k[m] * 64 + part * 8;
    float* outq = out + (size_t)b * CDIM * 1024 + hw0 + m;
    float lsum = 0.f;
    #pragma unroll
    for (int j = 0; j < 8; j++) {
        float4 ev = __ldg(erow + j);
        int c = part * 32 + j * 4;
        float qv[4] = {ev.x, ev.y, ev.z, ev.w};
        #pragma unroll
        for (int u = 0; u < 4; u++) {
            float zv = zrow[(c + u) * 33];
            float d  = __fsub_rn(qv[u], zv);
            outq[(size_t)(c + u) * 1024] = __fadd_rn(zv, d);
            lsum = __fmaf_rn(d, d, lsum);
        }
    }
    __syncthreads();           // s_bd reuse safety
    s_bd[tid] = lsum;
    __syncthreads();
    #pragma unroll
    for (int st = 128; st; st >>= 1) {
        if (tid < st) s_bd[tid] += s_bd[tid + st];
        __syncthreads();
    }
    if (tid == 0) g_partial[blockIdx.x] = s_bd[0];
}

__global__ void finalize_kernel(float* __restrict__ out) {
    __shared__ float red[256];
    red[threadIdx.x] = g_partial[threadIdx.x] + g_partial[threadIdx.x + 256];
    __syncthreads();
    #pragma unroll
    for (int st = 128; st; st >>= 1) {
        if (threadIdx.x < st) red[threadIdx.x] += red[threadIdx.x + st];
        __syncthreads();
    }
    if (threadIdx.x == 0) {
        const size_t QELEMS = (size_t)NROWS * CDIM;
        float loss = red[0] / (float)QELEMS;
        out[QELEMS]     = loss;
        out[QELEMS + 1] = 0.25f * loss;
    }
}

// ---------------------------------------------------------------------------
extern "C" void kernel_launch(void* const* d_in, const int* in_sizes, int n_in,
                              void* d_out, int out_size) {
    const float* z   = (const float*)d_in[0];
    const float* emb = (const float*)d_in[1];
    float* out = (float*)d_out;

    constexpr int PREP_SMEM = 66560;
    constexpr int RESC_SMEM = (256 * 33 + 512 + 32 + 32 * CLIST + 32) * 4;  // ~40 KB
    cudaFuncSetAttribute(gemm_screen_kernel,
                         cudaFuncAttributeMaxDynamicSharedMemorySize, SM_TOTAL);
    cudaFuncSetAttribute(conv_az_kernel,
                         cudaFuncAttributeMaxDynamicSharedMemorySize, PREP_SMEM);
    cudaFuncSetAttribute(conv_bc_kernel,
                         cudaFuncAttributeMaxDynamicSharedMemorySize, PREP_SMEM);
    cudaFuncSetAttribute(rescore_quant_kernel,
                         cudaFuncAttributeMaxDynamicSharedMemorySize, RESC_SMEM);

    conv_az_kernel<<<NROWS / 64, 256, PREP_SMEM>>>(z);
    conv_bc_kernel<<<KCODES / 64, 256, PREP_SMEM>>>(emb);
    gemm_screen_kernel<<<NROWS / MT, GTHREADS, SM_TOTAL>>>();
    rescore_quant_kernel<<<NROWS / 32, 256, RESC_SMEM>>>(z, emb, out);
    finalize_kernel<<<1, 256>>>(out);
}